// round 5
// baseline (speedup 1.0000x reference)
#include <cuda_runtime.h>
#include <cuda_bf16.h>
#include <cstdint>

#define Bb 8
#define Ff 16
#define Pp 196
#define Dd 768
#define Hh 12
#define HD 64
#define NTOK (Bb*Ff*Pp)          // 25088
#define QKVW (3*Dd)              // 2304
#define GK 768                   // K for all GEMMs
#define NCH (GK/16)              // 48 K-chunks of 16

// ---------------- scratch (allocation-free: __device__ globals) ----------------
__device__ float g_qkv[(size_t)NTOK * QKVW];   // 231 MB
__device__ float g_attn[(size_t)NTOK * Dd];    // 77 MB
__device__ float g_y[(size_t)NTOK * Dd];       // 77 MB
__device__ float g_x1[(size_t)NTOK * Dd];      // 77 MB
__device__ float g_wt[(size_t)Dd * QKVW];      // 7 MB (transposed weight)

typedef unsigned long long u64;

__device__ __forceinline__ u64 pack2(float x, float y) {
    u64 d;
    asm("mov.b64 %0, {%1, %2};" : "=l"(d) : "f"(x), "f"(y));
    return d;
}
__device__ __forceinline__ void unpack2(u64 v, float& x, float& y) {
    asm("mov.b64 {%0, %1}, %2;" : "=f"(x), "=f"(y) : "l"(v));
}
__device__ __forceinline__ void fma2(u64& acc, u64 a, u64 b) {
    asm("fma.rn.f32x2 %0, %1, %2, %0;" : "+l"(acc) : "l"(a), "l"(b));
}

// ---------------- weight transpose: out[N,K] = in[K,N] ----------------
__global__ __launch_bounds__(256) void transpose32(
    const float* __restrict__ in, float* __restrict__ out, int K, int N)
{
    __shared__ float t[32][33];
    int n0 = blockIdx.x * 32, k0 = blockIdx.y * 32;
    int tx = threadIdx.x, ty = threadIdx.y;   // 32 x 8
#pragma unroll
    for (int j = 0; j < 32; j += 8)
        t[ty + j][tx] = in[(size_t)(k0 + ty + j) * N + n0 + tx];
    __syncthreads();
#pragma unroll
    for (int j = 0; j < 32; j += 8)
        out[(size_t)(n0 + ty + j) * K + k0 + tx] = t[tx][ty + j];
}

// ---------------- FFMA2 SGEMM: C[M,N] = A[M,768] @ Bt[N,768]^T + bias --------
// 128x128 CTA tile, BK=16, 256 threads, 8x8 micro-tile as 4x8 f32x2 (M-pairs).
#define BKg 16
__global__ __launch_bounds__(256) void gemm_f2(
    const float* __restrict__ A, const float* __restrict__ Bt,
    const float* __restrict__ bias, float* __restrict__ C, int N)
{
    __shared__ float As[2][BKg][128];
    __shared__ float Bs[2][BKg][136];

    int tid = threadIdx.x;
    int ty = tid >> 4, tx = tid & 15;
    int m0 = ty * 8, n0 = tx * 8;
    int bm = blockIdx.y * 128, bn = blockIdx.x * 128;

    // staging: lane-distinct rows -> conflict-free STS
    int sr = tid & 127;            // row 0..127
    int sh = (tid >> 7) * 8;       // k-half 0 or 8

    const float* Ag = A  + (size_t)(bm + sr) * GK + sh;
    const float* Bg = Bt + (size_t)(bn + sr) * GK + sh;

    u64 acc[4][8];
#pragma unroll
    for (int p = 0; p < 4; p++)
#pragma unroll
        for (int n = 0; n < 8; n++) acc[p][n] = 0ull;

    float4 pa0, pa1, pb0, pb1;
    pa0 = *(const float4*)(Ag + 0);
    pa1 = *(const float4*)(Ag + 4);
    pb0 = *(const float4*)(Bg + 0);
    pb1 = *(const float4*)(Bg + 4);
    {
        float va[8] = {pa0.x, pa0.y, pa0.z, pa0.w, pa1.x, pa1.y, pa1.z, pa1.w};
        float vb[8] = {pb0.x, pb0.y, pb0.z, pb0.w, pb1.x, pb1.y, pb1.z, pb1.w};
#pragma unroll
        for (int j = 0; j < 8; j++) {
            As[0][sh + j][sr] = va[j];
            Bs[0][sh + j][sr] = vb[j];
        }
    }
    __syncthreads();

    for (int ch = 0; ch < NCH; ch++) {
        int st = ch & 1;
        if (ch + 1 < NCH) {
            const float* Ap = Ag + (ch + 1) * BKg;
            const float* Bp = Bg + (ch + 1) * BKg;
            pa0 = *(const float4*)(Ap + 0);
            pa1 = *(const float4*)(Ap + 4);
            pb0 = *(const float4*)(Bp + 0);
            pb1 = *(const float4*)(Bp + 4);
        }
#pragma unroll
        for (int kk = 0; kk < BKg; kk++) {
            u64 a2[4];
#pragma unroll
            for (int p = 0; p < 4; p++)
                a2[p] = *(const u64*)(&As[st][kk][m0 + 2 * p]);
            float4 bv0 = *(const float4*)(&Bs[st][kk][n0]);
            float4 bv1 = *(const float4*)(&Bs[st][kk][n0 + 4]);
            u64 b2[8];
            b2[0] = pack2(bv0.x, bv0.x); b2[1] = pack2(bv0.y, bv0.y);
            b2[2] = pack2(bv0.z, bv0.z); b2[3] = pack2(bv0.w, bv0.w);
            b2[4] = pack2(bv1.x, bv1.x); b2[5] = pack2(bv1.y, bv1.y);
            b2[6] = pack2(bv1.z, bv1.z); b2[7] = pack2(bv1.w, bv1.w);
#pragma unroll
            for (int p = 0; p < 4; p++)
#pragma unroll
                for (int n = 0; n < 8; n++)
                    fma2(acc[p][n], a2[p], b2[n]);
        }
        if (ch + 1 < NCH) {
            int ns = (ch + 1) & 1;
            float va[8] = {pa0.x, pa0.y, pa0.z, pa0.w, pa1.x, pa1.y, pa1.z, pa1.w};
            float vb[8] = {pb0.x, pb0.y, pb0.z, pb0.w, pb1.x, pb1.y, pb1.z, pb1.w};
#pragma unroll
            for (int j = 0; j < 8; j++) {
                As[ns][sh + j][sr] = va[j];
                Bs[ns][sh + j][sr] = vb[j];
            }
            __syncthreads();
        }
    }

    // epilogue
    float bb[8];
#pragma unroll
    for (int n = 0; n < 8; n++) bb[n] = bias[bn + n0 + n];
#pragma unroll
    for (int p = 0; p < 4; p++) {
        float lo[8], hi[8];
#pragma unroll
        for (int n = 0; n < 8; n++) {
            unpack2(acc[p][n], lo[n], hi[n]);
            lo[n] += bb[n]; hi[n] += bb[n];
        }
        size_t r0 = (size_t)(bm + m0 + 2 * p);
        float* c0 = C + r0 * N + bn + n0;
        float* c1 = c0 + N;
        *(float4*)(c0 + 0) = make_float4(lo[0], lo[1], lo[2], lo[3]);
        *(float4*)(c0 + 4) = make_float4(lo[4], lo[5], lo[6], lo[7]);
        *(float4*)(c1 + 0) = make_float4(hi[0], hi[1], hi[2], hi[3]);
        *(float4*)(c1 + 4) = make_float4(hi[4], hi[5], hi[6], hi[7]);
    }
}

// ---------------- generic small-seq attention ----------------
__global__ __launch_bounds__(256) void attn_kernel(
    const float* __restrict__ qkv, float* __restrict__ out, int S, int temporal)
{
    extern __shared__ float sm[];
    int h = blockIdx.y;
    int seq = blockIdx.x;
    int base, stride;
    if (temporal) {
        int b = seq / Pp, p = seq % Pp;
        base = b * Ff * Pp + p;
        stride = Pp;
    } else {
        base = seq * Pp;
        stride = 1;
    }

    float* Ks = sm;                 // S * 65
    float* Vs = Ks + S * 65;        // S * 64
    float* qs = Vs + S * 64;        // 64
    float* sc = qs + 64;            // S
    float* red = sc + S;            // 2

    int tid = threadIdx.x;

    for (int idx = tid; idx < S * 64; idx += 256) {
        int s = idx >> 6, d = idx & 63;
        size_t row = (size_t)(base + s * stride) * QKVW;
        Ks[s * 65 + d] = qkv[row + Dd + h * HD + d];
        Vs[s * 64 + d] = qkv[row + 2 * Dd + h * HD + d];
    }
    __syncthreads();

    for (int q = 0; q < S; q++) {
        size_t qrow = (size_t)(base + q * stride);
        if (tid < 64) qs[tid] = qkv[qrow * QKVW + h * HD + tid];
        __syncthreads();

        if (tid < S) {
            const float* kr = Ks + tid * 65;
            float acc = 0.f;
#pragma unroll 16
            for (int d = 0; d < 64; d++) acc += qs[d] * kr[d];
            sc[tid] = acc * 0.125f;
        }
        __syncthreads();

        if (tid < 32) {
            float m = -1e30f;
            for (int j = tid; j < S; j += 32) m = fmaxf(m, sc[j]);
#pragma unroll
            for (int o = 16; o; o >>= 1) m = fmaxf(m, __shfl_xor_sync(0xffffffffu, m, o));
            red[0] = m;
        }
        __syncthreads();
        float smax = red[0];
        if (tid < S) sc[tid] = __expf(sc[tid] - smax);
        __syncthreads();
        if (tid < 32) {
            float s = 0.f;
            for (int j = tid; j < S; j += 32) s += sc[j];
#pragma unroll
            for (int o = 16; o; o >>= 1) s += __shfl_xor_sync(0xffffffffu, s, o);
            red[1] = 1.0f / s;
        }
        __syncthreads();
        float inv = red[1];

        if (tid < 64) {
            float acc = 0.f;
            for (int j = 0; j < S; j++) acc += sc[j] * Vs[j * 64 + tid];
            out[qrow * Dd + h * HD + tid] = acc * inv;
        }
        __syncthreads();
    }
}

// ---------------- fused residual + LayerNorm ----------------
__global__ __launch_bounds__(256) void add_ln_kernel(
    const float* __restrict__ x, const float* __restrict__ y,
    const float* __restrict__ g, const float* __restrict__ b,
    float* __restrict__ out)
{
    __shared__ float row_sm[Dd];
    __shared__ float ps[8], ps2[8];
    __shared__ float red[2];

    size_t row = blockIdx.x;
    const float* xr = x + row * Dd;
    const float* yr = y + row * Dd;
    int tid = threadIdx.x;
    int lane = tid & 31, wid = tid >> 5;

    float s = 0.f, s2 = 0.f;
    for (int d = tid; d < Dd; d += 256) {
        float v = xr[d] + yr[d];
        row_sm[d] = v;
        s += v;
        s2 += v * v;
    }
#pragma unroll
    for (int o = 16; o; o >>= 1) {
        s  += __shfl_xor_sync(0xffffffffu, s, o);
        s2 += __shfl_xor_sync(0xffffffffu, s2, o);
    }
    if (lane == 0) { ps[wid] = s; ps2[wid] = s2; }
    __syncthreads();
    if (tid < 8) {
        s = ps[tid]; s2 = ps2[tid];
#pragma unroll
        for (int o = 4; o; o >>= 1) {
            s  += __shfl_xor_sync(0xffu, s, o);
            s2 += __shfl_xor_sync(0xffu, s2, o);
        }
        if (tid == 0) {
            float mean = s / Dd;
            float var = s2 / Dd - mean * mean;
            red[0] = mean;
            red[1] = rsqrtf(var + 1e-5f);
        }
    }
    __syncthreads();
    float mean = red[0], rstd = red[1];
    for (int d = tid; d < Dd; d += 256)
        out[row * Dd + d] = (row_sm[d] - mean) * rstd * g[d] + b[d];
}

// ---------------- launch ----------------
extern "C" void kernel_launch(void* const* d_in, const int* in_sizes, int n_in,
                              void* d_out, int out_size)
{
    const float* x      = (const float*)d_in[0];
    const float* Wqkv_t = (const float*)d_in[1];
    const float* bqkv_t = (const float*)d_in[2];
    const float* Wo_t   = (const float*)d_in[3];
    const float* bo_t   = (const float*)d_in[4];
    const float* Wqkv_s = (const float*)d_in[5];
    const float* bqkv_s = (const float*)d_in[6];
    const float* Wo_s   = (const float*)d_in[7];
    const float* bo_s   = (const float*)d_in[8];
    const float* g1     = (const float*)d_in[9];
    const float* b1     = (const float*)d_in[10];
    const float* g2     = (const float*)d_in[11];
    const float* b2     = (const float*)d_in[12];
    float* out = (float*)d_out;

    float *qkv, *attn, *y, *x1, *wt;
    cudaGetSymbolAddress((void**)&qkv,  g_qkv);
    cudaGetSymbolAddress((void**)&attn, g_attn);
    cudaGetSymbolAddress((void**)&y,    g_y);
    cudaGetSymbolAddress((void**)&x1,   g_x1);
    cudaGetSymbolAddress((void**)&wt,   g_wt);

    int smem_spatial  = (Pp * 65 + Pp * 64 + 64 + Pp + 2) * (int)sizeof(float);
    int smem_temporal = (Ff * 65 + Ff * 64 + 64 + Ff + 2) * (int)sizeof(float);
    cudaFuncSetAttribute(attn_kernel, cudaFuncAttributeMaxDynamicSharedMemorySize, smem_spatial);

    dim3 tb(32, 8);
    dim3 tg_qkv(QKVW / 32, GK / 32);      // (72, 24)
    dim3 tg_out(Dd / 32, GK / 32);        // (24, 24)
    dim3 gg_qkv(QKVW / 128, NTOK / 128);  // (18, 196)
    dim3 gg_out(Dd / 128, NTOK / 128);    // (6, 196)

    // temporal QKV projection
    transpose32<<<tg_qkv, tb>>>(Wqkv_t, wt, GK, QKVW);
    gemm_f2<<<gg_qkv, 256>>>(x, wt, bqkv_t, qkv, QKVW);
    // temporal attention (S=16)
    attn_kernel<<<dim3(Bb * Pp, Hh), 256, smem_temporal>>>(qkv, attn, Ff, 1);
    // temporal out-projection
    transpose32<<<tg_out, tb>>>(Wo_t, wt, GK, Dd);
    gemm_f2<<<gg_out, 256>>>(attn, wt, bo_t, y, Dd);
    // x1 = LN(x + y)
    add_ln_kernel<<<NTOK, 256>>>(x, y, g1, b1, x1);
    // spatial QKV projection
    transpose32<<<tg_qkv, tb>>>(Wqkv_s, wt, GK, QKVW);
    gemm_f2<<<gg_qkv, 256>>>(x1, wt, bqkv_s, qkv, QKVW);
    // spatial attention (S=196)
    attn_kernel<<<dim3(Bb * Ff, Hh), 256, smem_spatial>>>(qkv, attn, Pp, 0);
    // spatial out-projection
    transpose32<<<tg_out, tb>>>(Wo_s, wt, GK, Dd);
    gemm_f2<<<gg_out, 256>>>(attn, wt, bo_s, y, Dd);
    // out = LN(x1 + y)
    add_ln_kernel<<<NTOK, 256>>>(x1, y, g2, b2, out);
}

// round 6
// speedup vs baseline: 1.8714x; 1.8714x over previous
#include <cuda_runtime.h>
#include <cuda_bf16.h>
#include <cstdint>

#define Bb 8
#define Ff 16
#define Pp 196
#define Dd 768
#define Hh 12
#define HD 64
#define NTOK (Bb*Ff*Pp)          // 25088
#define QKVW (3*Dd)              // 2304
#define GK 768                   // K for all GEMMs
#define KCHUNKS (GK/32)          // 24

// ---------------- scratch (allocation-free: __device__ globals) ----------------
__device__ float         g_qkv[(size_t)NTOK * QKVW];   // 231 MB (f32: attention input)
__device__ float         g_y[(size_t)NTOK * Dd];       // 77 MB
__device__ float         g_x1[(size_t)NTOK * Dd];      // 77 MB
__device__ __nv_bfloat16 g_xb[(size_t)NTOK * Dd];      // 38.5 MB (bf16 GEMM operands)
__device__ __nv_bfloat16 g_x1b[(size_t)NTOK * Dd];     // 38.5 MB
__device__ __nv_bfloat16 g_attnb[(size_t)NTOK * Dd];   // 38.5 MB
__device__ __nv_bfloat16 g_wtb[(size_t)Dd * QKVW];     // 3.5 MB (transposed bf16 weight)

__device__ __forceinline__ void mma_bf16(float* c, const uint32_t* a, const uint32_t* b) {
    asm volatile(
        "mma.sync.aligned.m16n8k16.row.col.f32.bf16.bf16.f32 "
        "{%0,%1,%2,%3}, {%4,%5,%6,%7}, {%8,%9}, {%0,%1,%2,%3};"
        : "+f"(c[0]), "+f"(c[1]), "+f"(c[2]), "+f"(c[3])
        : "r"(a[0]), "r"(a[1]), "r"(a[2]), "r"(a[3]), "r"(b[0]), "r"(b[1]));
}

// ---------------- f32 -> bf16 convert ----------------
__global__ __launch_bounds__(256) void f2b_kernel(
    const float* __restrict__ in, __nv_bfloat16* __restrict__ out, int n4)
{
    int i = blockIdx.x * 256 + threadIdx.x;
    if (i < n4) {
        float4 v = *(const float4*)(in + (size_t)i * 4);
        __nv_bfloat162 p0 = __float22bfloat162_rn(make_float2(v.x, v.y));
        __nv_bfloat162 p1 = __float22bfloat162_rn(make_float2(v.z, v.w));
        uint2 u;
        u.x = *reinterpret_cast<uint32_t*>(&p0);
        u.y = *reinterpret_cast<uint32_t*>(&p1);
        *(uint2*)(out + (size_t)i * 4) = u;
    }
}

// ---------------- weight transpose to bf16: out[N,K] = bf16(in[K,N]) ----------
__global__ __launch_bounds__(256) void transpose_b(
    const float* __restrict__ in, __nv_bfloat16* __restrict__ out, int K, int N)
{
    __shared__ float t[32][33];
    int n0 = blockIdx.x * 32, k0 = blockIdx.y * 32;
    int tx = threadIdx.x, ty = threadIdx.y;   // 32 x 8
#pragma unroll
    for (int j = 0; j < 32; j += 8)
        t[ty + j][tx] = in[(size_t)(k0 + ty + j) * N + n0 + tx];
    __syncthreads();
#pragma unroll
    for (int j = 0; j < 32; j += 8)
        out[(size_t)(n0 + ty + j) * K + k0 + tx] = __float2bfloat16(t[tx][ty + j]);
}

// ---------------- BF16 mma.sync GEMM: C = A[M,768]bf16 @ Bt[N,768]bf16^T + bias
// 128x128 CTA tile, BK=32, 256 threads (8 warps 2x4, warp tile 64x32).
// Smem rows: 16 u32 (bf16x2) padded to 20 -> conflict-free fragment loads.
// 2 CTAs/SM for latency hiding.
#define ROWP32 20
#define STAGE_U (128 * ROWP32)       // u32 per operand per stage (2560)
__global__ __launch_bounds__(256, 2) void gemm_mma(
    const __nv_bfloat16* __restrict__ A, const __nv_bfloat16* __restrict__ Bt,
    const float* __restrict__ bias, float* __restrict__ C, int N)
{
    __shared__ uint32_t As[2][STAGE_U];
    __shared__ uint32_t Bs[2][STAGE_U];

    int tid = threadIdx.x;
    int wid = tid >> 5, lane = tid & 31;
    int wr = wid >> 2, wc = wid & 3;        // warp 2x4
    int lg = lane >> 2, lk = lane & 3;      // group-of-4 layout
    int bm = blockIdx.y * 128, bn = blockIdx.x * 128;

    int ldr = tid >> 1;                 // row 0..127
    int half = tid & 1;                 // which 16-bf16 half of the 32-chunk
    int ebase = half * 16;              // bf16 element offset
    int c2base = half * 8;              // u32 offset in smem row

    const __nv_bfloat16* Ag = A  + (size_t)(bm + ldr) * GK + ebase;
    const __nv_bfloat16* Bg = Bt + (size_t)(bn + ldr) * GK + ebase;

    float acc[4][4][4];
#pragma unroll
    for (int i = 0; i < 4; i++)
#pragma unroll
        for (int j = 0; j < 4; j++)
#pragma unroll
            for (int k = 0; k < 4; k++) acc[i][j][k] = 0.f;

    uint4 ra0, ra1, rb0, rb1;
    ra0 = *(const uint4*)(Ag);          // 8 bf16
    ra1 = *(const uint4*)(Ag + 8);
    rb0 = *(const uint4*)(Bg);
    rb1 = *(const uint4*)(Bg + 8);
    *(uint4*)(&As[0][ldr * ROWP32 + c2base])     = ra0;
    *(uint4*)(&As[0][ldr * ROWP32 + c2base + 4]) = ra1;
    *(uint4*)(&Bs[0][ldr * ROWP32 + c2base])     = rb0;
    *(uint4*)(&Bs[0][ldr * ROWP32 + c2base + 4]) = rb1;
    __syncthreads();

    for (int it = 0; it < KCHUNKS; it++) {
        if (it + 1 < KCHUNKS) {
            int kc = (it + 1) * 32;
            ra0 = *(const uint4*)(Ag + kc);
            ra1 = *(const uint4*)(Ag + kc + 8);
            rb0 = *(const uint4*)(Bg + kc);
            rb1 = *(const uint4*)(Bg + kc + 8);
        }
        const uint32_t* Au = As[it & 1];
        const uint32_t* Bu = Bs[it & 1];
#pragma unroll
        for (int ks = 0; ks < 2; ks++) {
            int c2 = ks * 8 + lk;
            uint32_t af[4][4], bf[4][2];
#pragma unroll
            for (int mt = 0; mt < 4; mt++) {
                int r = wr * 64 + mt * 16 + lg;
                af[mt][0] = Au[r * ROWP32 + c2];
                af[mt][1] = Au[(r + 8) * ROWP32 + c2];
                af[mt][2] = Au[r * ROWP32 + c2 + 4];
                af[mt][3] = Au[(r + 8) * ROWP32 + c2 + 4];
            }
#pragma unroll
            for (int nt = 0; nt < 4; nt++) {
                int n = wc * 32 + nt * 8 + lg;
                bf[nt][0] = Bu[n * ROWP32 + c2];
                bf[nt][1] = Bu[n * ROWP32 + c2 + 4];
            }
#pragma unroll
            for (int mt = 0; mt < 4; mt++)
#pragma unroll
                for (int nt = 0; nt < 4; nt++)
                    mma_bf16(acc[mt][nt], af[mt], bf[nt]);
        }
        if (it + 1 < KCHUNKS) {
            int st = (it + 1) & 1;
            *(uint4*)(&As[st][ldr * ROWP32 + c2base])     = ra0;
            *(uint4*)(&As[st][ldr * ROWP32 + c2base + 4]) = ra1;
            *(uint4*)(&Bs[st][ldr * ROWP32 + c2base])     = rb0;
            *(uint4*)(&Bs[st][ldr * ROWP32 + c2base + 4]) = rb1;
            __syncthreads();
        }
    }

    // epilogue: direct stores, float2 per (mt,nt) row pair
#pragma unroll
    for (int mt = 0; mt < 4; mt++) {
        size_t r0 = (size_t)(bm + wr * 64 + mt * 16 + lg);
#pragma unroll
        for (int nt = 0; nt < 4; nt++) {
            int c0 = bn + wc * 32 + nt * 8 + lk * 2;
            float bx = bias[c0], by = bias[c0 + 1];
            float2 v0 = make_float2(acc[mt][nt][0] + bx, acc[mt][nt][1] + by);
            float2 v1 = make_float2(acc[mt][nt][2] + bx, acc[mt][nt][3] + by);
            *(float2*)(C + r0 * N + c0) = v0;
            *(float2*)(C + (r0 + 8) * N + c0) = v1;
        }
    }
}

// ---------------- generic small-seq attention (bf16 output) ----------------
__global__ __launch_bounds__(256) void attn_kernel(
    const float* __restrict__ qkv, __nv_bfloat16* __restrict__ out, int S, int temporal)
{
    extern __shared__ float sm[];
    int h = blockIdx.y;
    int seq = blockIdx.x;
    int base, stride;
    if (temporal) {
        int b = seq / Pp, p = seq % Pp;
        base = b * Ff * Pp + p;
        stride = Pp;
    } else {
        base = seq * Pp;
        stride = 1;
    }

    float* Ks = sm;                 // S * 65
    float* Vs = Ks + S * 65;        // S * 64
    float* qs = Vs + S * 64;        // 64
    float* sc = qs + 64;            // S
    float* red = sc + S;            // 2

    int tid = threadIdx.x;

    for (int idx = tid; idx < S * 64; idx += 256) {
        int s = idx >> 6, d = idx & 63;
        size_t row = (size_t)(base + s * stride) * QKVW;
        Ks[s * 65 + d] = qkv[row + Dd + h * HD + d];
        Vs[s * 64 + d] = qkv[row + 2 * Dd + h * HD + d];
    }
    __syncthreads();

    for (int q = 0; q < S; q++) {
        size_t qrow = (size_t)(base + q * stride);
        if (tid < 64) qs[tid] = qkv[qrow * QKVW + h * HD + tid];
        __syncthreads();

        if (tid < S) {
            const float* kr = Ks + tid * 65;
            float acc = 0.f;
#pragma unroll 16
            for (int d = 0; d < 64; d++) acc += qs[d] * kr[d];
            sc[tid] = acc * 0.125f;
        }
        __syncthreads();

        if (tid < 32) {
            float m = -1e30f;
            for (int j = tid; j < S; j += 32) m = fmaxf(m, sc[j]);
#pragma unroll
            for (int o = 16; o; o >>= 1) m = fmaxf(m, __shfl_xor_sync(0xffffffffu, m, o));
            red[0] = m;
        }
        __syncthreads();
        float smax = red[0];
        if (tid < S) sc[tid] = __expf(sc[tid] - smax);
        __syncthreads();
        if (tid < 32) {
            float s = 0.f;
            for (int j = tid; j < S; j += 32) s += sc[j];
#pragma unroll
            for (int o = 16; o; o >>= 1) s += __shfl_xor_sync(0xffffffffu, s, o);
            red[1] = 1.0f / s;
        }
        __syncthreads();
        float inv = red[1];

        if (tid < 64) {
            float acc = 0.f;
            for (int j = 0; j < S; j++) acc += sc[j] * Vs[j * 64 + tid];
            out[qrow * Dd + h * HD + tid] = __float2bfloat16(acc * inv);
        }
        __syncthreads();
    }
}

// ---------------- fused residual + LayerNorm (+ optional bf16 copy) ----------
__global__ __launch_bounds__(256) void add_ln_kernel(
    const float* __restrict__ x, const float* __restrict__ y,
    const float* __restrict__ g, const float* __restrict__ b,
    float* __restrict__ out, __nv_bfloat16* __restrict__ outb, int wb)
{
    __shared__ float row_sm[Dd];
    __shared__ float ps[8], ps2[8];
    __shared__ float red[2];

    size_t row = blockIdx.x;
    const float* xr = x + row * Dd;
    const float* yr = y + row * Dd;
    int tid = threadIdx.x;
    int lane = tid & 31, wid = tid >> 5;

    float s = 0.f, s2 = 0.f;
    for (int d = tid; d < Dd; d += 256) {
        float v = xr[d] + yr[d];
        row_sm[d] = v;
        s += v;
        s2 += v * v;
    }
#pragma unroll
    for (int o = 16; o; o >>= 1) {
        s  += __shfl_xor_sync(0xffffffffu, s, o);
        s2 += __shfl_xor_sync(0xffffffffu, s2, o);
    }
    if (lane == 0) { ps[wid] = s; ps2[wid] = s2; }
    __syncthreads();
    if (tid < 8) {
        s = ps[tid]; s2 = ps2[tid];
#pragma unroll
        for (int o = 4; o; o >>= 1) {
            s  += __shfl_xor_sync(0xffu, s, o);
            s2 += __shfl_xor_sync(0xffu, s2, o);
        }
        if (tid == 0) {
            float mean = s / Dd;
            float var = s2 / Dd - mean * mean;
            red[0] = mean;
            red[1] = rsqrtf(var + 1e-5f);
        }
    }
    __syncthreads();
    float mean = red[0], rstd = red[1];
    for (int d = tid; d < Dd; d += 256) {
        float v = (row_sm[d] - mean) * rstd * g[d] + b[d];
        out[row * Dd + d] = v;
        if (wb) outb[row * Dd + d] = __float2bfloat16(v);
    }
}

// ---------------- launch ----------------
extern "C" void kernel_launch(void* const* d_in, const int* in_sizes, int n_in,
                              void* d_out, int out_size)
{
    const float* x      = (const float*)d_in[0];
    const float* Wqkv_t = (const float*)d_in[1];
    const float* bqkv_t = (const float*)d_in[2];
    const float* Wo_t   = (const float*)d_in[3];
    const float* bo_t   = (const float*)d_in[4];
    const float* Wqkv_s = (const float*)d_in[5];
    const float* bqkv_s = (const float*)d_in[6];
    const float* Wo_s   = (const float*)d_in[7];
    const float* bo_s   = (const float*)d_in[8];
    const float* g1     = (const float*)d_in[9];
    const float* b1     = (const float*)d_in[10];
    const float* g2     = (const float*)d_in[11];
    const float* b2     = (const float*)d_in[12];
    float* out = (float*)d_out;

    float *qkv, *y, *x1;
    __nv_bfloat16 *xb, *x1b, *attnb, *wtb;
    cudaGetSymbolAddress((void**)&qkv,   g_qkv);
    cudaGetSymbolAddress((void**)&y,     g_y);
    cudaGetSymbolAddress((void**)&x1,    g_x1);
    cudaGetSymbolAddress((void**)&xb,    g_xb);
    cudaGetSymbolAddress((void**)&x1b,   g_x1b);
    cudaGetSymbolAddress((void**)&attnb, g_attnb);
    cudaGetSymbolAddress((void**)&wtb,   g_wtb);

    int smem_spatial  = (Pp * 65 + Pp * 64 + 64 + Pp + 2) * (int)sizeof(float);
    int smem_temporal = (Ff * 65 + Ff * 64 + 64 + Ff + 2) * (int)sizeof(float);
    cudaFuncSetAttribute(attn_kernel, cudaFuncAttributeMaxDynamicSharedMemorySize, smem_spatial);

    dim3 tb(32, 8);
    dim3 tg_qkv(QKVW / 32, GK / 32);      // (72, 24)
    dim3 tg_out(Dd / 32, GK / 32);        // (24, 24)
    dim3 gg_qkv(QKVW / 128, NTOK / 128);  // (18, 196)
    dim3 gg_out(Dd / 128, NTOK / 128);    // (6, 196)
    int n4 = NTOK * Dd / 4;

    // x -> bf16
    f2b_kernel<<<(n4 + 255) / 256, 256>>>(x, xb, n4);
    // temporal QKV projection
    transpose_b<<<tg_qkv, tb>>>(Wqkv_t, wtb, GK, QKVW);
    gemm_mma<<<gg_qkv, 256>>>(xb, wtb, bqkv_t, qkv, QKVW);
    // temporal attention (S=16)
    attn_kernel<<<dim3(Bb * Pp, Hh), 256, smem_temporal>>>(qkv, attnb, Ff, 1);
    // temporal out-projection
    transpose_b<<<tg_out, tb>>>(Wo_t, wtb, GK, Dd);
    gemm_mma<<<gg_out, 256>>>(attnb, wtb, bo_t, y, Dd);
    // x1 = LN(x + y)  (+ bf16 copy)
    add_ln_kernel<<<NTOK, 256>>>(x, y, g1, b1, x1, x1b, 1);
    // spatial QKV projection
    transpose_b<<<tg_qkv, tb>>>(Wqkv_s, wtb, GK, QKVW);
    gemm_mma<<<gg_qkv, 256>>>(x1b, wtb, bqkv_s, qkv, QKVW);
    // spatial attention (S=196)
    attn_kernel<<<dim3(Bb * Ff, Hh), 256, smem_spatial>>>(qkv, attnb, Pp, 0);
    // spatial out-projection
    transpose_b<<<tg_out, tb>>>(Wo_s, wtb, GK, Dd);
    gemm_mma<<<gg_out, 256>>>(attnb, wtb, bo_s, y, Dd);
    // out = LN(x1 + y)
    add_ln_kernel<<<NTOK, 256>>>(x1, y, g2, b2, out, (__nv_bfloat16*)nullptr, 0);
}

// round 8
// speedup vs baseline: 2.0994x; 1.1218x over previous
#include <cuda_runtime.h>
#include <cuda_bf16.h>
#include <cstdint>

#define Bb 8
#define Ff 16
#define Pp 196
#define Dd 768
#define Hh 12
#define HD 64
#define NTOK (Bb*Ff*Pp)          // 25088
#define QKVW (3*Dd)              // 2304
#define GK 768                   // K for all GEMMs
#define KCHUNKS (GK/32)          // 24

// ---------------- scratch (allocation-free: __device__ globals) ----------------
__device__ float         g_qkv[(size_t)NTOK * QKVW];   // 231 MB (f32: attention input)
__device__ float         g_y[(size_t)NTOK * Dd];       // 77 MB
__device__ float         g_x1[(size_t)NTOK * Dd];      // 77 MB
__device__ __nv_bfloat16 g_xb[(size_t)NTOK * Dd];      // 38.5 MB (bf16 GEMM operands)
__device__ __nv_bfloat16 g_x1b[(size_t)NTOK * Dd];     // 38.5 MB
__device__ __nv_bfloat16 g_attnb[(size_t)NTOK * Dd];   // 38.5 MB
__device__ __nv_bfloat16 g_wtb[(size_t)Dd * QKVW];     // 3.5 MB (transposed bf16 weight)

__device__ __forceinline__ void mma_bf16(float* c, const uint32_t* a, const uint32_t* b) {
    asm volatile(
        "mma.sync.aligned.m16n8k16.row.col.f32.bf16.bf16.f32 "
        "{%0,%1,%2,%3}, {%4,%5,%6,%7}, {%8,%9}, {%0,%1,%2,%3};"
        : "+f"(c[0]), "+f"(c[1]), "+f"(c[2]), "+f"(c[3])
        : "r"(a[0]), "r"(a[1]), "r"(a[2]), "r"(a[3]), "r"(b[0]), "r"(b[1]));
}
__device__ __forceinline__ uint32_t smem_u32(const void* p) {
    uint32_t a;
    asm("{ .reg .u64 t; cvta.to.shared.u64 t, %1; cvt.u32.u64 %0, t; }" : "=r"(a) : "l"(p));
    return a;
}
__device__ __forceinline__ void cp16(uint32_t dst, const void* src) {
    asm volatile("cp.async.cg.shared.global [%0], [%1], 16;" :: "r"(dst), "l"(src));
}
#define CP_COMMIT() asm volatile("cp.async.commit_group;" ::: "memory")
#define CP_WAIT1()  asm volatile("cp.async.wait_group 1;" ::: "memory")

// ---------------- f32 -> bf16 convert ----------------
__global__ __launch_bounds__(256) void f2b_kernel(
    const float* __restrict__ in, __nv_bfloat16* __restrict__ out, int n4)
{
    int i = blockIdx.x * 256 + threadIdx.x;
    if (i < n4) {
        float4 v = *(const float4*)(in + (size_t)i * 4);
        __nv_bfloat162 p0 = __float22bfloat162_rn(make_float2(v.x, v.y));
        __nv_bfloat162 p1 = __float22bfloat162_rn(make_float2(v.z, v.w));
        uint2 u;
        u.x = *reinterpret_cast<uint32_t*>(&p0);
        u.y = *reinterpret_cast<uint32_t*>(&p1);
        *(uint2*)(out + (size_t)i * 4) = u;
    }
}

// ---------------- weight transpose to bf16: out[N,K] = bf16(in[K,N]) ----------
__global__ __launch_bounds__(256) void transpose_b(
    const float* __restrict__ in, __nv_bfloat16* __restrict__ out, int K, int N)
{
    __shared__ float t[32][33];
    int n0 = blockIdx.x * 32, k0 = blockIdx.y * 32;
    int tx = threadIdx.x, ty = threadIdx.y;   // 32 x 8
#pragma unroll
    for (int j = 0; j < 32; j += 8)
        t[ty + j][tx] = in[(size_t)(k0 + ty + j) * N + n0 + tx];
    __syncthreads();
#pragma unroll
    for (int j = 0; j < 32; j += 8)
        out[(size_t)(n0 + ty + j) * K + k0 + tx] = __float2bfloat16(t[tx][ty + j]);
}

// ---------------- BF16 mma.sync GEMM with 3-stage cp.async pipeline ----------
// 128x128 CTA tile, BK=32, 256 threads (8 warps 2x4, warp tile 64x32), 2 CTA/SM.
#define ROWP32 20
#define STAGE_U (128 * ROWP32)       // u32 per operand per stage (2560)
#define NSTG 3
__global__ __launch_bounds__(256, 2) void gemm_mma(
    const __nv_bfloat16* __restrict__ A, const __nv_bfloat16* __restrict__ Bt,
    const float* __restrict__ bias, float* __restrict__ C, int N)
{
    __shared__ __align__(16) uint32_t As[NSTG][STAGE_U];
    __shared__ __align__(16) uint32_t Bs[NSTG][STAGE_U];

    int tid = threadIdx.x;
    int wid = tid >> 5, lane = tid & 31;
    int wr = wid >> 2, wc = wid & 3;        // warp 2x4
    int lg = lane >> 2, lk = lane & 3;      // group-of-4 layout
    int bm = blockIdx.y * 128, bn = blockIdx.x * 128;

    int ldr = tid >> 1;                 // row 0..127
    int half = tid & 1;                 // which 16-bf16 half of the 32-chunk
    int ebase = half * 16;              // bf16 element offset
    int c2base = half * 8;              // u32 offset in smem row

    const __nv_bfloat16* Ag = A  + (size_t)(bm + ldr) * GK + ebase;
    const __nv_bfloat16* Bg = Bt + (size_t)(bn + ldr) * GK + ebase;

    uint32_t sAs = smem_u32(&As[0][0]);
    uint32_t sBs = smem_u32(&Bs[0][0]);
    uint32_t soff = (uint32_t)(ldr * ROWP32 + c2base) * 4;

    float acc[4][4][4];
#pragma unroll
    for (int i = 0; i < 4; i++)
#pragma unroll
        for (int j = 0; j < 4; j++)
#pragma unroll
            for (int k = 0; k < 4; k++) acc[i][j][k] = 0.f;

    // prologue: issue stages 0 and 1
#pragma unroll
    for (int s = 0; s < 2; s++) {
        int kc = s * 32;
        uint32_t ab = sAs + s * (STAGE_U * 4) + soff;
        uint32_t bb = sBs + s * (STAGE_U * 4) + soff;
        cp16(ab,      Ag + kc);
        cp16(ab + 16, Ag + kc + 8);
        cp16(bb,      Bg + kc);
        cp16(bb + 16, Bg + kc + 8);
        CP_COMMIT();
    }

    for (int it = 0; it < KCHUNKS; it++) {
        CP_WAIT1();
        __syncthreads();
        const uint32_t* Au = As[it % NSTG];
        const uint32_t* Bu = Bs[it % NSTG];
#pragma unroll
        for (int ks = 0; ks < 2; ks++) {
            int c2 = ks * 8 + lk;
            uint32_t af[4][4], bf[4][2];
#pragma unroll
            for (int mt = 0; mt < 4; mt++) {
                int r = wr * 64 + mt * 16 + lg;
                af[mt][0] = Au[r * ROWP32 + c2];
                af[mt][1] = Au[(r + 8) * ROWP32 + c2];
                af[mt][2] = Au[r * ROWP32 + c2 + 4];
                af[mt][3] = Au[(r + 8) * ROWP32 + c2 + 4];
            }
#pragma unroll
            for (int nt = 0; nt < 4; nt++) {
                int n = wc * 32 + nt * 8 + lg;
                bf[nt][0] = Bu[n * ROWP32 + c2];
                bf[nt][1] = Bu[n * ROWP32 + c2 + 4];
            }
#pragma unroll
            for (int mt = 0; mt < 4; mt++)
#pragma unroll
                for (int nt = 0; nt < 4; nt++)
                    mma_bf16(acc[mt][nt], af[mt], bf[nt]);
        }
        __syncthreads();
        if (it + 2 < KCHUNKS) {
            int s = (it + 2) % NSTG;
            int kc = (it + 2) * 32;
            uint32_t ab = sAs + s * (STAGE_U * 4) + soff;
            uint32_t bb = sBs + s * (STAGE_U * 4) + soff;
            cp16(ab,      Ag + kc);
            cp16(ab + 16, Ag + kc + 8);
            cp16(bb,      Bg + kc);
            cp16(bb + 16, Bg + kc + 8);
        }
        CP_COMMIT();   // keep group count in lockstep even when empty
    }

    // epilogue
#pragma unroll
    for (int mt = 0; mt < 4; mt++) {
        size_t r0 = (size_t)(bm + wr * 64 + mt * 16 + lg);
#pragma unroll
        for (int nt = 0; nt < 4; nt++) {
            int c0 = bn + wc * 32 + nt * 8 + lk * 2;
            float bx = bias[c0], by = bias[c0 + 1];
            float2 v0 = make_float2(acc[mt][nt][0] + bx, acc[mt][nt][1] + by);
            float2 v1 = make_float2(acc[mt][nt][2] + bx, acc[mt][nt][3] + by);
            *(float2*)(C + r0 * N + c0) = v0;
            *(float2*)(C + (r0 + 8) * N + c0) = v1;
        }
    }
}

// ---------------- temporal attention, S=16: fully parallel ----------------
// One block per (b, p, head). Thread (q,k) computes one score; softmax via
// half-warp shuffles; output 4 per thread. Rows padded to 68 floats so
// float4 loads stay 16B-aligned.
__global__ __launch_bounds__(256) void attn16_kernel(
    const float* __restrict__ qkv, __nv_bfloat16* __restrict__ out)
{
    __shared__ __align__(16) float Qs[16][68];
    __shared__ __align__(16) float Ks[16][68];
    __shared__ __align__(16) float Vs[16][64];
    __shared__ float Ps[16][17];

    int h = blockIdx.y;
    int seq = blockIdx.x;
    int b = seq / Pp, p = seq % Pp;
    int base = b * Ff * Pp + p;          // + f*Pp per frame
    int tid = threadIdx.x;

    // stage Q, K, V: 1024 elems each, 256 threads x 4
#pragma unroll
    for (int i = 0; i < 4; i++) {
        int idx = i * 256 + tid;
        int f = idx >> 6, d = idx & 63;
        size_t row = (size_t)(base + f * Pp) * QKVW + h * HD + d;
        Qs[f][d] = qkv[row];
        Ks[f][d] = qkv[row + Dd];
        Vs[f][d] = qkv[row + 2 * Dd];
    }
    __syncthreads();

    // scores: thread = (q, k)
    {
        int q = tid >> 4, k = tid & 15;
        float acc = 0.f;
#pragma unroll
        for (int d4 = 0; d4 < 16; d4++) {
            float4 kv = *(const float4*)(&Ks[k][d4 * 4]);
            float4 qv = *(const float4*)(&Qs[q][d4 * 4]);
            acc += qv.x * kv.x + qv.y * kv.y + qv.z * kv.z + qv.w * kv.w;
        }
        acc *= 0.125f;
        // softmax across the 16 k-lanes (one half-warp)
        float m = acc;
#pragma unroll
        for (int o = 8; o; o >>= 1) m = fmaxf(m, __shfl_xor_sync(0xffffffffu, m, o));
        float e = __expf(acc - m);
        float s = e;
#pragma unroll
        for (int o = 8; o; o >>= 1) s += __shfl_xor_sync(0xffffffffu, s, o);
        Ps[q][k] = e / s;
    }
    __syncthreads();

    // output: thread t -> d = t&63, q in {4*(t>>6) .. +3}
    {
        int d = tid & 63;
        int q0 = (tid >> 6) * 4;
        float a0 = 0.f, a1 = 0.f, a2 = 0.f, a3 = 0.f;
#pragma unroll
        for (int k = 0; k < 16; k++) {
            float v = Vs[k][d];
            a0 += Ps[q0 + 0][k] * v;
            a1 += Ps[q0 + 1][k] * v;
            a2 += Ps[q0 + 2][k] * v;
            a3 += Ps[q0 + 3][k] * v;
        }
        size_t o0 = (size_t)(base + (q0 + 0) * Pp) * Dd + h * HD + d;
        out[o0]                       = __float2bfloat16(a0);
        out[o0 + (size_t)Pp * Dd]     = __float2bfloat16(a1);
        out[o0 + (size_t)2 * Pp * Dd] = __float2bfloat16(a2);
        out[o0 + (size_t)3 * Pp * Dd] = __float2bfloat16(a3);
    }
}

// ---------------- generic attention (spatial, S=196) ----------------
__global__ __launch_bounds__(256) void attn_kernel(
    const float* __restrict__ qkv, __nv_bfloat16* __restrict__ out, int S)
{
    extern __shared__ float sm[];
    int h = blockIdx.y;
    int base = blockIdx.x * Pp;

    float* Ks = sm;                 // S * 65
    float* Vs = Ks + S * 65;        // S * 64
    float* qs = Vs + S * 64;        // 64
    float* sc = qs + 64;            // S
    float* red = sc + S;            // 2

    int tid = threadIdx.x;

    for (int idx = tid; idx < S * 64; idx += 256) {
        int s = idx >> 6, d = idx & 63;
        size_t row = (size_t)(base + s) * QKVW;
        Ks[s * 65 + d] = qkv[row + Dd + h * HD + d];
        Vs[s * 64 + d] = qkv[row + 2 * Dd + h * HD + d];
    }
    __syncthreads();

    for (int q = 0; q < S; q++) {
        size_t qrow = (size_t)(base + q);
        if (tid < 64) qs[tid] = qkv[qrow * QKVW + h * HD + tid];
        __syncthreads();

        if (tid < S) {
            const float* kr = Ks + tid * 65;
            float acc = 0.f;
#pragma unroll 16
            for (int d = 0; d < 64; d++) acc += qs[d] * kr[d];
            sc[tid] = acc * 0.125f;
        }
        __syncthreads();

        if (tid < 32) {
            float m = -1e30f;
            for (int j = tid; j < S; j += 32) m = fmaxf(m, sc[j]);
#pragma unroll
            for (int o = 16; o; o >>= 1) m = fmaxf(m, __shfl_xor_sync(0xffffffffu, m, o));
            red[0] = m;
        }
        __syncthreads();
        float smax = red[0];
        if (tid < S) sc[tid] = __expf(sc[tid] - smax);
        __syncthreads();
        if (tid < 32) {
            float s = 0.f;
            for (int j = tid; j < S; j += 32) s += sc[j];
#pragma unroll
            for (int o = 16; o; o >>= 1) s += __shfl_xor_sync(0xffffffffu, s, o);
            red[1] = 1.0f / s;
        }
        __syncthreads();
        float inv = red[1];

        if (tid < 64) {
            float acc = 0.f;
            for (int j = 0; j < S; j++) acc += sc[j] * Vs[j * 64 + tid];
            out[qrow * Dd + h * HD + tid] = __float2bfloat16(acc * inv);
        }
        __syncthreads();
    }
}

// ---------------- fused residual + LayerNorm (+ optional bf16 copy) ----------
__global__ __launch_bounds__(256) void add_ln_kernel(
    const float* __restrict__ x, const float* __restrict__ y,
    const float* __restrict__ g, const float* __restrict__ b,
    float* __restrict__ out, __nv_bfloat16* __restrict__ outb, int wb)
{
    __shared__ float row_sm[Dd];
    __shared__ float ps[8], ps2[8];
    __shared__ float red[2];

    size_t row = blockIdx.x;
    const float* xr = x + row * Dd;
    const float* yr = y + row * Dd;
    int tid = threadIdx.x;
    int lane = tid & 31, wid = tid >> 5;

    float s = 0.f, s2 = 0.f;
    for (int d = tid; d < Dd; d += 256) {
        float v = xr[d] + yr[d];
        row_sm[d] = v;
        s += v;
        s2 += v * v;
    }
#pragma unroll
    for (int o = 16; o; o >>= 1) {
        s  += __shfl_xor_sync(0xffffffffu, s, o);
        s2 += __shfl_xor_sync(0xffffffffu, s2, o);
    }
    if (lane == 0) { ps[wid] = s; ps2[wid] = s2; }
    __syncthreads();
    if (tid < 8) {
        s = ps[tid]; s2 = ps2[tid];
#pragma unroll
        for (int o = 4; o; o >>= 1) {
            s  += __shfl_xor_sync(0xffu, s, o);
            s2 += __shfl_xor_sync(0xffu, s2, o);
        }
        if (tid == 0) {
            float mean = s / Dd;
            float var = s2 / Dd - mean * mean;
            red[0] = mean;
            red[1] = rsqrtf(var + 1e-5f);
        }
    }
    __syncthreads();
    float mean = red[0], rstd = red[1];
    for (int d = tid; d < Dd; d += 256) {
        float v = (row_sm[d] - mean) * rstd * g[d] + b[d];
        out[row * Dd + d] = v;
        if (wb) outb[row * Dd + d] = __float2bfloat16(v);
    }
}

// ---------------- launch ----------------
extern "C" void kernel_launch(void* const* d_in, const int* in_sizes, int n_in,
                              void* d_out, int out_size)
{
    const float* x      = (const float*)d_in[0];
    const float* Wqkv_t = (const float*)d_in[1];
    const float* bqkv_t = (const float*)d_in[2];
    const float* Wo_t   = (const float*)d_in[3];
    const float* bo_t   = (const float*)d_in[4];
    const float* Wqkv_s = (const float*)d_in[5];
    const float* bqkv_s = (const float*)d_in[6];
    const float* Wo_s   = (const float*)d_in[7];
    const float* bo_s   = (const float*)d_in[8];
    const float* g1     = (const float*)d_in[9];
    const float* b1     = (const float*)d_in[10];
    const float* g2     = (const float*)d_in[11];
    const float* b2     = (const float*)d_in[12];
    float* out = (float*)d_out;

    float *qkv, *y, *x1;
    __nv_bfloat16 *xb, *x1b, *attnb, *wtb;
    cudaGetSymbolAddress((void**)&qkv,   g_qkv);
    cudaGetSymbolAddress((void**)&y,     g_y);
    cudaGetSymbolAddress((void**)&x1,    g_x1);
    cudaGetSymbolAddress((void**)&xb,    g_xb);
    cudaGetSymbolAddress((void**)&x1b,   g_x1b);
    cudaGetSymbolAddress((void**)&attnb, g_attnb);
    cudaGetSymbolAddress((void**)&wtb,   g_wtb);

    int smem_spatial = (Pp * 65 + Pp * 64 + 64 + Pp + 2) * (int)sizeof(float);
    cudaFuncSetAttribute(attn_kernel, cudaFuncAttributeMaxDynamicSharedMemorySize, smem_spatial);

    dim3 tb(32, 8);
    dim3 tg_qkv(QKVW / 32, GK / 32);      // (72, 24)
    dim3 tg_out(Dd / 32, GK / 32);        // (24, 24)
    dim3 gg_qkv(QKVW / 128, NTOK / 128);  // (18, 196)
    dim3 gg_out(Dd / 128, NTOK / 128);    // (6, 196)
    int n4 = NTOK * Dd / 4;

    // x -> bf16
    f2b_kernel<<<(n4 + 255) / 256, 256>>>(x, xb, n4);
    // temporal QKV projection
    transpose_b<<<tg_qkv, tb>>>(Wqkv_t, wtb, GK, QKVW);
    gemm_mma<<<gg_qkv, 256>>>(xb, wtb, bqkv_t, qkv, QKVW);
    // temporal attention (S=16), fully parallel
    attn16_kernel<<<dim3(Bb * Pp, Hh), 256>>>(qkv, attnb);
    // temporal out-projection
    transpose_b<<<tg_out, tb>>>(Wo_t, wtb, GK, Dd);
    gemm_mma<<<gg_out, 256>>>(attnb, wtb, bo_t, y, Dd);
    // x1 = LN(x + y)  (+ bf16 copy)
    add_ln_kernel<<<NTOK, 256>>>(x, y, g1, b1, x1, x1b, 1);
    // spatial QKV projection
    transpose_b<<<tg_qkv, tb>>>(Wqkv_s, wtb, GK, QKVW);
    gemm_mma<<<gg_qkv, 256>>>(x1b, wtb, bqkv_s, qkv, QKVW);
    // spatial attention (S=196)
    attn_kernel<<<dim3(Bb * Ff, Hh), 256, smem_spatial>>>(qkv, attnb, Pp);
    // spatial out-projection
    transpose_b<<<tg_out, tb>>>(Wo_s, wtb, GK, Dd);
    gemm_mma<<<gg_out, 256>>>(attnb, wtb, bo_s, y, Dd);
    // out = LN(x1 + y)
    add_ln_kernel<<<NTOK, 256>>>(x1, y, g2, b2, out, (__nv_bfloat16*)nullptr, 0);
}

// round 9
// speedup vs baseline: 7.4644x; 3.5555x over previous
#include <cuda_runtime.h>
#include <cuda_bf16.h>
#include <cstdint>

#define Bb 8
#define Ff 16
#define Pp 196
#define Dd 768
#define Hh 12
#define HD 64
#define NTOK (Bb*Ff*Pp)          // 25088
#define QKVW (3*Dd)              // 2304
#define GK 768                   // K for all GEMMs
#define KCHUNKS (GK/32)          // 24

// ---------------- scratch (allocation-free: __device__ globals) ----------------
__device__ float         g_qkv[(size_t)NTOK * QKVW];   // 231 MB (f32: attention input)
__device__ float         g_y[(size_t)NTOK * Dd];       // 77 MB
__device__ float         g_x1[(size_t)NTOK * Dd];      // 77 MB
__device__ __nv_bfloat16 g_xb[(size_t)NTOK * Dd];      // 38.5 MB (bf16 GEMM operands)
__device__ __nv_bfloat16 g_x1b[(size_t)NTOK * Dd];     // 38.5 MB
__device__ __nv_bfloat16 g_attnb[(size_t)NTOK * Dd];   // 38.5 MB
__device__ __nv_bfloat16 g_wtb[(size_t)Dd * QKVW];     // 3.5 MB (transposed bf16 weight)

__device__ __forceinline__ void mma_bf16(float* c, const uint32_t* a, const uint32_t* b) {
    asm volatile(
        "mma.sync.aligned.m16n8k16.row.col.f32.bf16.bf16.f32 "
        "{%0,%1,%2,%3}, {%4,%5,%6,%7}, {%8,%9}, {%0,%1,%2,%3};"
        : "+f"(c[0]), "+f"(c[1]), "+f"(c[2]), "+f"(c[3])
        : "r"(a[0]), "r"(a[1]), "r"(a[2]), "r"(a[3]), "r"(b[0]), "r"(b[1]));
}
__device__ __forceinline__ uint32_t smem_u32(const void* p) {
    uint32_t a;
    asm("{ .reg .u64 t; cvta.to.shared.u64 t, %1; cvt.u32.u64 %0, t; }" : "=r"(a) : "l"(p));
    return a;
}
__device__ __forceinline__ void cp16(uint32_t dst, const void* src) {
    asm volatile("cp.async.cg.shared.global [%0], [%1], 16;" :: "r"(dst), "l"(src));
}
#define CP_COMMIT() asm volatile("cp.async.commit_group;" ::: "memory")
#define CP_WAIT1()  asm volatile("cp.async.wait_group 1;" ::: "memory")

__device__ __forceinline__ uint32_t packbf(float lo, float hi) {
    __nv_bfloat162 p = __float22bfloat162_rn(make_float2(lo, hi));
    return *reinterpret_cast<uint32_t*>(&p);
}

// ---------------- f32 -> bf16 convert ----------------
__global__ __launch_bounds__(256) void f2b_kernel(
    const float* __restrict__ in, __nv_bfloat16* __restrict__ out, int n4)
{
    int i = blockIdx.x * 256 + threadIdx.x;
    if (i < n4) {
        float4 v = *(const float4*)(in + (size_t)i * 4);
        uint2 u;
        u.x = packbf(v.x, v.y);
        u.y = packbf(v.z, v.w);
        *(uint2*)(out + (size_t)i * 4) = u;
    }
}

// ---------------- weight transpose to bf16: out[N,K] = bf16(in[K,N]) ----------
__global__ __launch_bounds__(256) void transpose_b(
    const float* __restrict__ in, __nv_bfloat16* __restrict__ out, int K, int N)
{
    __shared__ float t[32][33];
    int n0 = blockIdx.x * 32, k0 = blockIdx.y * 32;
    int tx = threadIdx.x, ty = threadIdx.y;   // 32 x 8
#pragma unroll
    for (int j = 0; j < 32; j += 8)
        t[ty + j][tx] = in[(size_t)(k0 + ty + j) * N + n0 + tx];
    __syncthreads();
#pragma unroll
    for (int j = 0; j < 32; j += 8)
        out[(size_t)(n0 + ty + j) * K + k0 + tx] = __float2bfloat16(t[tx][ty + j]);
}

// ---------------- BF16 mma.sync GEMM with 3-stage cp.async pipeline ----------
#define ROWP32 20
#define STAGE_U (128 * ROWP32)
#define NSTG 3
__global__ __launch_bounds__(256, 2) void gemm_mma(
    const __nv_bfloat16* __restrict__ A, const __nv_bfloat16* __restrict__ Bt,
    const float* __restrict__ bias, float* __restrict__ C, int N)
{
    __shared__ __align__(16) uint32_t As[NSTG][STAGE_U];
    __shared__ __align__(16) uint32_t Bs[NSTG][STAGE_U];

    int tid = threadIdx.x;
    int wid = tid >> 5, lane = tid & 31;
    int wr = wid >> 2, wc = wid & 3;
    int lg = lane >> 2, lk = lane & 3;
    int bm = blockIdx.y * 128, bn = blockIdx.x * 128;

    int ldr = tid >> 1;
    int half = tid & 1;
    int ebase = half * 16;
    int c2base = half * 8;

    const __nv_bfloat16* Ag = A  + (size_t)(bm + ldr) * GK + ebase;
    const __nv_bfloat16* Bg = Bt + (size_t)(bn + ldr) * GK + ebase;

    uint32_t sAs = smem_u32(&As[0][0]);
    uint32_t sBs = smem_u32(&Bs[0][0]);
    uint32_t soff = (uint32_t)(ldr * ROWP32 + c2base) * 4;

    float acc[4][4][4];
#pragma unroll
    for (int i = 0; i < 4; i++)
#pragma unroll
        for (int j = 0; j < 4; j++)
#pragma unroll
            for (int k = 0; k < 4; k++) acc[i][j][k] = 0.f;

#pragma unroll
    for (int s = 0; s < 2; s++) {
        int kc = s * 32;
        uint32_t ab = sAs + s * (STAGE_U * 4) + soff;
        uint32_t bb = sBs + s * (STAGE_U * 4) + soff;
        cp16(ab,      Ag + kc);
        cp16(ab + 16, Ag + kc + 8);
        cp16(bb,      Bg + kc);
        cp16(bb + 16, Bg + kc + 8);
        CP_COMMIT();
    }

    for (int it = 0; it < KCHUNKS; it++) {
        CP_WAIT1();
        __syncthreads();
        const uint32_t* Au = As[it % NSTG];
        const uint32_t* Bu = Bs[it % NSTG];
#pragma unroll
        for (int ks = 0; ks < 2; ks++) {
            int c2 = ks * 8 + lk;
            uint32_t af[4][4], bf[4][2];
#pragma unroll
            for (int mt = 0; mt < 4; mt++) {
                int r = wr * 64 + mt * 16 + lg;
                af[mt][0] = Au[r * ROWP32 + c2];
                af[mt][1] = Au[(r + 8) * ROWP32 + c2];
                af[mt][2] = Au[r * ROWP32 + c2 + 4];
                af[mt][3] = Au[(r + 8) * ROWP32 + c2 + 4];
            }
#pragma unroll
            for (int nt = 0; nt < 4; nt++) {
                int n = wc * 32 + nt * 8 + lg;
                bf[nt][0] = Bu[n * ROWP32 + c2];
                bf[nt][1] = Bu[n * ROWP32 + c2 + 4];
            }
#pragma unroll
            for (int mt = 0; mt < 4; mt++)
#pragma unroll
                for (int nt = 0; nt < 4; nt++)
                    mma_bf16(acc[mt][nt], af[mt], bf[nt]);
        }
        __syncthreads();
        if (it + 2 < KCHUNKS) {
            int s = (it + 2) % NSTG;
            int kc = (it + 2) * 32;
            uint32_t ab = sAs + s * (STAGE_U * 4) + soff;
            uint32_t bb = sBs + s * (STAGE_U * 4) + soff;
            cp16(ab,      Ag + kc);
            cp16(ab + 16, Ag + kc + 8);
            cp16(bb,      Bg + kc);
            cp16(bb + 16, Bg + kc + 8);
        }
        CP_COMMIT();
    }

#pragma unroll
    for (int mt = 0; mt < 4; mt++) {
        size_t r0 = (size_t)(bm + wr * 64 + mt * 16 + lg);
#pragma unroll
        for (int nt = 0; nt < 4; nt++) {
            int c0 = bn + wc * 32 + nt * 8 + lk * 2;
            float bx = bias[c0], by = bias[c0 + 1];
            float2 v0 = make_float2(acc[mt][nt][0] + bx, acc[mt][nt][1] + by);
            float2 v1 = make_float2(acc[mt][nt][2] + bx, acc[mt][nt][3] + by);
            *(float2*)(C + r0 * N + c0) = v0;
            *(float2*)(C + (r0 + 8) * N + c0) = v1;
        }
    }
}

// ---------------- temporal attention, S=16 (unchanged from round 8) ----------
__global__ __launch_bounds__(256) void attn16_kernel(
    const float* __restrict__ qkv, __nv_bfloat16* __restrict__ out)
{
    __shared__ __align__(16) float Qs[16][68];
    __shared__ __align__(16) float Ks[16][68];
    __shared__ __align__(16) float Vs[16][64];
    __shared__ float Ps[16][17];

    int h = blockIdx.y;
    int seq = blockIdx.x;
    int b = seq / Pp, p = seq % Pp;
    int base = b * Ff * Pp + p;
    int tid = threadIdx.x;

#pragma unroll
    for (int i = 0; i < 4; i++) {
        int idx = i * 256 + tid;
        int f = idx >> 6, d = idx & 63;
        size_t row = (size_t)(base + f * Pp) * QKVW + h * HD + d;
        Qs[f][d] = qkv[row];
        Ks[f][d] = qkv[row + Dd];
        Vs[f][d] = qkv[row + 2 * Dd];
    }
    __syncthreads();

    {
        int q = tid >> 4, k = tid & 15;
        float acc = 0.f;
#pragma unroll
        for (int d4 = 0; d4 < 16; d4++) {
            float4 kv = *(const float4*)(&Ks[k][d4 * 4]);
            float4 qv = *(const float4*)(&Qs[q][d4 * 4]);
            acc += qv.x * kv.x + qv.y * kv.y + qv.z * kv.z + qv.w * kv.w;
        }
        acc *= 0.125f;
        float m = acc;
#pragma unroll
        for (int o = 8; o; o >>= 1) m = fmaxf(m, __shfl_xor_sync(0xffffffffu, m, o));
        float e = __expf(acc - m);
        float s = e;
#pragma unroll
        for (int o = 8; o; o >>= 1) s += __shfl_xor_sync(0xffffffffu, s, o);
        Ps[q][k] = e / s;
    }
    __syncthreads();

    {
        int d = tid & 63;
        int q0 = (tid >> 6) * 4;
        float a0 = 0.f, a1 = 0.f, a2 = 0.f, a3 = 0.f;
#pragma unroll
        for (int k = 0; k < 16; k++) {
            float v = Vs[k][d];
            a0 += Ps[q0 + 0][k] * v;
            a1 += Ps[q0 + 1][k] * v;
            a2 += Ps[q0 + 2][k] * v;
            a3 += Ps[q0 + 3][k] * v;
        }
        size_t o0 = (size_t)(base + (q0 + 0) * Pp) * Dd + h * HD + d;
        out[o0]                       = __float2bfloat16(a0);
        out[o0 + (size_t)Pp * Dd]     = __float2bfloat16(a1);
        out[o0 + (size_t)2 * Pp * Dd] = __float2bfloat16(a2);
        out[o0 + (size_t)3 * Pp * Dd] = __float2bfloat16(a3);
    }
}

// ---------------- spatial attention, S=196 padded to 208, bf16 MMA ----------
// One block per (b*F+f, head). 8 warps; warp owns 16-query M-tiles (13 tiles,
// round-robin). Scores in registers, in-register masked softmax, P passed as
// MMA A-fragments directly from the score C-fragments, PV via transposed V.
#define SPAD 208
#define QRU 36     // u32 per Q/K/V smem row (32 data + 4 pad)
#define VTR 108    // u32 per Vt row (104 data + 4 pad)
__global__ __launch_bounds__(256) void attn196_kernel(
    const float* __restrict__ qkv, __nv_bfloat16* __restrict__ out)
{
    extern __shared__ __align__(16) uint32_t sm196[];
    uint32_t* Qu = sm196;                 // [208][36]
    uint32_t* Ku = Qu + SPAD * QRU;       // [208][36]
    uint32_t* Vu = Ku + SPAD * QRU;       // [208][36]
    uint32_t* Tu = Vu + SPAD * QRU;       // Vt: [64][108]

    int h = blockIdx.y;
    int base = blockIdx.x * Pp;
    int tid = threadIdx.x;
    int wid = tid >> 5, lane = tid & 31;
    int lg = lane >> 2, lk = lane & 3;

    // stage Q, K, V as bf16 (rows >= 196 zeroed)
    for (int i = tid; i < SPAD * 32; i += 256) {
        int s = i >> 5, d2 = i & 31;
        uint32_t qv = 0, kv = 0, vv = 0;
        if (s < Pp) {
            const float* row = qkv + (size_t)(base + s) * QKVW + h * HD + d2 * 2;
            float2 q2 = *(const float2*)(row);
            float2 k2 = *(const float2*)(row + Dd);
            float2 v2 = *(const float2*)(row + 2 * Dd);
            qv = packbf(q2.x, q2.y);
            kv = packbf(k2.x, k2.y);
            vv = packbf(v2.x, v2.y);
        }
        Qu[s * QRU + d2] = qv;
        Ku[s * QRU + d2] = kv;
        Vu[s * QRU + d2] = vv;
    }
    __syncthreads();

    // transpose V (bf16) -> Tu[d][key-pair]
    {
        const __nv_bfloat16* vb = (const __nv_bfloat16*)Vu;
        for (int i = tid; i < 64 * 104; i += 256) {
            int d = i & 63, s2 = i >> 6;
            uint32_t lo = *(const uint16_t*)(vb + (2 * s2) * (QRU * 2) + d);
            uint32_t hi = *(const uint16_t*)(vb + (2 * s2 + 1) * (QRU * 2) + d);
            Tu[d * VTR + s2] = lo | (hi << 16);
        }
    }
    __syncthreads();

    for (int mt = wid; mt < 13; mt += 8) {
        int r = mt * 16 + lg;

        // Q A-fragments: 4 k16 chunks
        uint32_t qa[4][4];
#pragma unroll
        for (int kc = 0; kc < 4; kc++) {
            int c2 = kc * 8 + lk;
            qa[kc][0] = Qu[r * QRU + c2];
            qa[kc][1] = Qu[(r + 8) * QRU + c2];
            qa[kc][2] = Qu[r * QRU + c2 + 4];
            qa[kc][3] = Qu[(r + 8) * QRU + c2 + 4];
        }

        // scores: 26 n8 tiles
        float sc[26][4];
#pragma unroll
        for (int nt = 0; nt < 26; nt++) {
            sc[nt][0] = sc[nt][1] = sc[nt][2] = sc[nt][3] = 0.f;
        }
#pragma unroll
        for (int nt = 0; nt < 26; nt++) {
            int n = nt * 8 + lg;
#pragma unroll
            for (int kc = 0; kc < 4; kc++) {
                uint32_t b[2];
                b[0] = Ku[n * QRU + kc * 8 + lk];
                b[1] = Ku[n * QRU + kc * 8 + lk + 4];
                mma_bf16(sc[nt], qa[kc], b);
            }
        }

        // scale + mask (cols >= 196)
#pragma unroll
        for (int nt = 0; nt < 26; nt++) {
            int col0 = nt * 8 + 2 * lk;
            sc[nt][0] = (col0     < Pp) ? sc[nt][0] * 0.125f : -1e30f;
            sc[nt][1] = (col0 + 1 < Pp) ? sc[nt][1] * 0.125f : -1e30f;
            sc[nt][2] = (col0     < Pp) ? sc[nt][2] * 0.125f : -1e30f;
            sc[nt][3] = (col0 + 1 < Pp) ? sc[nt][3] * 0.125f : -1e30f;
        }

        // row max (row lg: regs 0,1; row lg+8: regs 2,3); quad shuffle
        float m0 = -1e30f, m1 = -1e30f;
#pragma unroll
        for (int nt = 0; nt < 26; nt++) {
            m0 = fmaxf(m0, fmaxf(sc[nt][0], sc[nt][1]));
            m1 = fmaxf(m1, fmaxf(sc[nt][2], sc[nt][3]));
        }
        m0 = fmaxf(m0, __shfl_xor_sync(0xffffffffu, m0, 1));
        m0 = fmaxf(m0, __shfl_xor_sync(0xffffffffu, m0, 2));
        m1 = fmaxf(m1, __shfl_xor_sync(0xffffffffu, m1, 1));
        m1 = fmaxf(m1, __shfl_xor_sync(0xffffffffu, m1, 2));

        // exp + row sum
        float s0 = 0.f, s1 = 0.f;
#pragma unroll
        for (int nt = 0; nt < 26; nt++) {
            sc[nt][0] = __expf(sc[nt][0] - m0); s0 += sc[nt][0];
            sc[nt][1] = __expf(sc[nt][1] - m0); s0 += sc[nt][1];
            sc[nt][2] = __expf(sc[nt][2] - m1); s1 += sc[nt][2];
            sc[nt][3] = __expf(sc[nt][3] - m1); s1 += sc[nt][3];
        }
        s0 += __shfl_xor_sync(0xffffffffu, s0, 1);
        s0 += __shfl_xor_sync(0xffffffffu, s0, 2);
        s1 += __shfl_xor_sync(0xffffffffu, s1, 1);
        s1 += __shfl_xor_sync(0xffffffffu, s1, 2);

        // pack P into MMA A-fragment layout (C-layout == A-layout)
        uint32_t pk[13][4];
#pragma unroll
        for (int j = 0; j < 13; j++) {
            pk[j][0] = packbf(sc[2 * j][0],     sc[2 * j][1]);
            pk[j][1] = packbf(sc[2 * j][2],     sc[2 * j][3]);
            pk[j][2] = packbf(sc[2 * j + 1][0], sc[2 * j + 1][1]);
            pk[j][3] = packbf(sc[2 * j + 1][2], sc[2 * j + 1][3]);
        }

        // PV: out[16, 64] = P[16, 208] @ Vt^T
        float oa[8][4];
#pragma unroll
        for (int nd = 0; nd < 8; nd++)
            oa[nd][0] = oa[nd][1] = oa[nd][2] = oa[nd][3] = 0.f;
#pragma unroll
        for (int j = 0; j < 13; j++) {
#pragma unroll
            for (int nd = 0; nd < 8; nd++) {
                int n = nd * 8 + lg;
                uint32_t b[2];
                b[0] = Tu[n * VTR + j * 8 + lk];
                b[1] = Tu[n * VTR + j * 8 + lk + 4];
                mma_bf16(oa[nd], pk[j], b);
            }
        }

        // normalize + store (bf16 pairs)
        float inv0 = 1.0f / s0, inv1 = 1.0f / s1;
        int row0 = r, row1 = r + 8;
#pragma unroll
        for (int nd = 0; nd < 8; nd++) {
            int col = nd * 8 + 2 * lk;
            if (row0 < Pp) {
                uint32_t u = packbf(oa[nd][0] * inv0, oa[nd][1] * inv0);
                *(uint32_t*)(out + (size_t)(base + row0) * Dd + h * HD + col) = u;
            }
            if (row1 < Pp) {
                uint32_t u = packbf(oa[nd][2] * inv1, oa[nd][3] * inv1);
                *(uint32_t*)(out + (size_t)(base + row1) * Dd + h * HD + col) = u;
            }
        }
    }
}

// ---------------- fused residual + LayerNorm (+ optional bf16 copy) ----------
__global__ __launch_bounds__(256) void add_ln_kernel(
    const float* __restrict__ x, const float* __restrict__ y,
    const float* __restrict__ g, const float* __restrict__ b,
    float* __restrict__ out, __nv_bfloat16* __restrict__ outb, int wb)
{
    __shared__ float row_sm[Dd];
    __shared__ float ps[8], ps2[8];
    __shared__ float red[2];

    size_t row = blockIdx.x;
    const float* xr = x + row * Dd;
    const float* yr = y + row * Dd;
    int tid = threadIdx.x;
    int lane = tid & 31, wid = tid >> 5;

    float s = 0.f, s2 = 0.f;
    for (int d = tid; d < Dd; d += 256) {
        float v = xr[d] + yr[d];
        row_sm[d] = v;
        s += v;
        s2 += v * v;
    }
#pragma unroll
    for (int o = 16; o; o >>= 1) {
        s  += __shfl_xor_sync(0xffffffffu, s, o);
        s2 += __shfl_xor_sync(0xffffffffu, s2, o);
    }
    if (lane == 0) { ps[wid] = s; ps2[wid] = s2; }
    __syncthreads();
    if (tid < 8) {
        s = ps[tid]; s2 = ps2[tid];
#pragma unroll
        for (int o = 4; o; o >>= 1) {
            s  += __shfl_xor_sync(0xffu, s, o);
            s2 += __shfl_xor_sync(0xffu, s2, o);
        }
        if (tid == 0) {
            float mean = s / Dd;
            float var = s2 / Dd - mean * mean;
            red[0] = mean;
            red[1] = rsqrtf(var + 1e-5f);
        }
    }
    __syncthreads();
    float mean = red[0], rstd = red[1];
    for (int d = tid; d < Dd; d += 256) {
        float v = (row_sm[d] - mean) * rstd * g[d] + b[d];
        out[row * Dd + d] = v;
        if (wb) outb[row * Dd + d] = __float2bfloat16(v);
    }
}

// ---------------- launch ----------------
extern "C" void kernel_launch(void* const* d_in, const int* in_sizes, int n_in,
                              void* d_out, int out_size)
{
    const float* x      = (const float*)d_in[0];
    const float* Wqkv_t = (const float*)d_in[1];
    const float* bqkv_t = (const float*)d_in[2];
    const float* Wo_t   = (const float*)d_in[3];
    const float* bo_t   = (const float*)d_in[4];
    const float* Wqkv_s = (const float*)d_in[5];
    const float* bqkv_s = (const float*)d_in[6];
    const float* Wo_s   = (const float*)d_in[7];
    const float* bo_s   = (const float*)d_in[8];
    const float* g1     = (const float*)d_in[9];
    const float* b1     = (const float*)d_in[10];
    const float* g2     = (const float*)d_in[11];
    const float* b2     = (const float*)d_in[12];
    float* out = (float*)d_out;

    float *qkv, *y, *x1;
    __nv_bfloat16 *xb, *x1b, *attnb, *wtb;
    cudaGetSymbolAddress((void**)&qkv,   g_qkv);
    cudaGetSymbolAddress((void**)&y,     g_y);
    cudaGetSymbolAddress((void**)&x1,    g_x1);
    cudaGetSymbolAddress((void**)&xb,    g_xb);
    cudaGetSymbolAddress((void**)&x1b,   g_x1b);
    cudaGetSymbolAddress((void**)&attnb, g_attnb);
    cudaGetSymbolAddress((void**)&wtb,   g_wtb);

    const int SMEM196 = (3 * SPAD * QRU + 64 * VTR) * (int)sizeof(uint32_t);  // 117504
    cudaFuncSetAttribute(attn196_kernel, cudaFuncAttributeMaxDynamicSharedMemorySize, SMEM196);

    dim3 tb(32, 8);
    dim3 tg_qkv(QKVW / 32, GK / 32);      // (72, 24)
    dim3 tg_out(Dd / 32, GK / 32);        // (24, 24)
    dim3 gg_qkv(QKVW / 128, NTOK / 128);  // (18, 196)
    dim3 gg_out(Dd / 128, NTOK / 128);    // (6, 196)
    int n4 = NTOK * Dd / 4;

    // x -> bf16
    f2b_kernel<<<(n4 + 255) / 256, 256>>>(x, xb, n4);
    // temporal QKV projection
    transpose_b<<<tg_qkv, tb>>>(Wqkv_t, wtb, GK, QKVW);
    gemm_mma<<<gg_qkv, 256>>>(xb, wtb, bqkv_t, qkv, QKVW);
    // temporal attention (S=16)
    attn16_kernel<<<dim3(Bb * Pp, Hh), 256>>>(qkv, attnb);
    // temporal out-projection
    transpose_b<<<tg_out, tb>>>(Wo_t, wtb, GK, Dd);
    gemm_mma<<<gg_out, 256>>>(attnb, wtb, bo_t, y, Dd);
    // x1 = LN(x + y)  (+ bf16 copy)
    add_ln_kernel<<<NTOK, 256>>>(x, y, g1, b1, x1, x1b, 1);
    // spatial QKV projection
    transpose_b<<<tg_qkv, tb>>>(Wqkv_s, wtb, GK, QKVW);
    gemm_mma<<<gg_qkv, 256>>>(x1b, wtb, bqkv_s, qkv, QKVW);
    // spatial attention (S=196), bf16 MMA flash-style
    attn196_kernel<<<dim3(Bb * Ff, Hh), 256, SMEM196>>>(qkv, attnb);
    // spatial out-projection
    transpose_b<<<tg_out, tb>>>(Wo_s, wtb, GK, Dd);
    gemm_mma<<<gg_out, 256>>>(attnb, wtb, bo_s, y, Dd);
    // out = LN(x1 + y)
    add_ln_kernel<<<NTOK, 256>>>(x1, y, g2, b2, out, (__nv_bfloat16*)nullptr, 0);
}

// round 10
// speedup vs baseline: 8.1581x; 1.0929x over previous
#include <cuda_runtime.h>
#include <cuda_bf16.h>
#include <cstdint>

#define Bb 8
#define Ff 16
#define Pp 196
#define Dd 768
#define Hh 12
#define HD 64
#define NTOK (Bb*Ff*Pp)          // 25088
#define QKVW (3*Dd)              // 2304
#define GK 768                   // K for all GEMMs
#define KCHUNKS (GK/32)          // 24

// ---------------- scratch (allocation-free: __device__ globals) ----------------
__device__ float         g_qkv[(size_t)NTOK * QKVW];   // 231 MB (f32: attention input)
__device__ float         g_y[(size_t)NTOK * Dd];       // 77 MB
__device__ float         g_x1[(size_t)NTOK * Dd];      // 77 MB
__device__ __nv_bfloat16 g_xb[(size_t)NTOK * Dd];      // 38.5 MB (bf16 GEMM operands)
__device__ __nv_bfloat16 g_x1b[(size_t)NTOK * Dd];     // 38.5 MB
__device__ __nv_bfloat16 g_attnb[(size_t)NTOK * Dd];   // 38.5 MB
__device__ __nv_bfloat16 g_wtb[(size_t)Dd * QKVW];     // 3.5 MB (transposed bf16 weight)

__device__ __forceinline__ void mma_bf16(float* c, const uint32_t* a, const uint32_t* b) {
    asm volatile(
        "mma.sync.aligned.m16n8k16.row.col.f32.bf16.bf16.f32 "
        "{%0,%1,%2,%3}, {%4,%5,%6,%7}, {%8,%9}, {%0,%1,%2,%3};"
        : "+f"(c[0]), "+f"(c[1]), "+f"(c[2]), "+f"(c[3])
        : "r"(a[0]), "r"(a[1]), "r"(a[2]), "r"(a[3]), "r"(b[0]), "r"(b[1]));
}
__device__ __forceinline__ void ldsm_x4(uint32_t* r, uint32_t addr) {
    asm volatile("ldmatrix.sync.aligned.m8n8.x4.shared.b16 {%0,%1,%2,%3}, [%4];"
        : "=r"(r[0]), "=r"(r[1]), "=r"(r[2]), "=r"(r[3]) : "r"(addr));
}
__device__ __forceinline__ uint32_t smem_u32(const void* p) {
    uint32_t a;
    asm("{ .reg .u64 t; cvta.to.shared.u64 t, %1; cvt.u32.u64 %0, t; }" : "=r"(a) : "l"(p));
    return a;
}
__device__ __forceinline__ void cp16(uint32_t dst, const void* src) {
    asm volatile("cp.async.cg.shared.global [%0], [%1], 16;" :: "r"(dst), "l"(src));
}
#define CP_COMMIT() asm volatile("cp.async.commit_group;" ::: "memory")
#define CP_WAIT1()  asm volatile("cp.async.wait_group 1;" ::: "memory")

__device__ __forceinline__ uint32_t packbf(float lo, float hi) {
    __nv_bfloat162 p = __float22bfloat162_rn(make_float2(lo, hi));
    return *reinterpret_cast<uint32_t*>(&p);
}

// ---------------- f32 -> bf16 convert ----------------
__global__ __launch_bounds__(256) void f2b_kernel(
    const float* __restrict__ in, __nv_bfloat16* __restrict__ out, int n4)
{
    int i = blockIdx.x * 256 + threadIdx.x;
    if (i < n4) {
        float4 v = *(const float4*)(in + (size_t)i * 4);
        uint2 u;
        u.x = packbf(v.x, v.y);
        u.y = packbf(v.z, v.w);
        *(uint2*)(out + (size_t)i * 4) = u;
    }
}

// ---------------- weight transpose to bf16: out[N,K] = bf16(in[K,N]) ----------
__global__ __launch_bounds__(256) void transpose_b(
    const float* __restrict__ in, __nv_bfloat16* __restrict__ out, int K, int N)
{
    __shared__ float t[32][33];
    int n0 = blockIdx.x * 32, k0 = blockIdx.y * 32;
    int tx = threadIdx.x, ty = threadIdx.y;   // 32 x 8
#pragma unroll
    for (int j = 0; j < 32; j += 8)
        t[ty + j][tx] = in[(size_t)(k0 + ty + j) * N + n0 + tx];
    __syncthreads();
#pragma unroll
    for (int j = 0; j < 32; j += 8)
        out[(size_t)(n0 + ty + j) * K + k0 + tx] = __float2bfloat16(t[tx][ty + j]);
}

// ---------------- BF16 mma.sync GEMM, cp.async pipeline + ldmatrix -----------
// 128x128 CTA tile, BK=32, 256 threads (8 warps 2x4, warp tile 64x32), 2 CTA/SM.
// Smem rows: 16 u32 (bf16x2) padded to 20 (80 B) -> LDSM phases conflict-free.
#define ROWP32 20
#define STAGE_U (128 * ROWP32)
#define NSTG 3
__global__ __launch_bounds__(256, 2) void gemm_mma(
    const __nv_bfloat16* __restrict__ A, const __nv_bfloat16* __restrict__ Bt,
    const float* __restrict__ bias, float* __restrict__ C, int N)
{
    __shared__ __align__(16) uint32_t As[NSTG][STAGE_U];
    __shared__ __align__(16) uint32_t Bs[NSTG][STAGE_U];

    int tid = threadIdx.x;
    int wid = tid >> 5, lane = tid & 31;
    int wr = wid >> 2, wc = wid & 3;
    int lg = lane >> 2, lk = lane & 3;
    int bm = blockIdx.y * 128, bn = blockIdx.x * 128;

    int ldr = tid >> 1;
    int half = tid & 1;
    int ebase = half * 16;
    int c2base = half * 8;

    const __nv_bfloat16* Ag = A  + (size_t)(bm + ldr) * GK + ebase;
    const __nv_bfloat16* Bg = Bt + (size_t)(bn + ldr) * GK + ebase;

    uint32_t sAs = smem_u32(&As[0][0]);
    uint32_t sBs = smem_u32(&Bs[0][0]);
    uint32_t soff = (uint32_t)(ldr * ROWP32 + c2base) * 4;

    // ldmatrix lane-address offsets (bytes, within a stage)
    // A (per mt): row = wr*64 + mt*16 + (lane&15), col16 = (lane>=16)*16
    uint32_t a_off = (uint32_t)((wr * 64 + (lane & 15)) * 80 + ((lane >> 4) & 1) * 16);
    // B (per nt-pair j): row = wc*32 + j*16 + (lane&7) + (lane>=16)*8, col16 = ((lane>>3)&1)*16
    uint32_t b_off = (uint32_t)((wc * 32 + (lane & 7) + ((lane >> 4) & 1) * 8) * 80
                                + ((lane >> 3) & 1) * 16);

    float acc[4][4][4];
#pragma unroll
    for (int i = 0; i < 4; i++)
#pragma unroll
        for (int j = 0; j < 4; j++)
#pragma unroll
            for (int k = 0; k < 4; k++) acc[i][j][k] = 0.f;

#pragma unroll
    for (int s = 0; s < 2; s++) {
        int kc = s * 32;
        uint32_t ab = sAs + s * (STAGE_U * 4) + soff;
        uint32_t bb = sBs + s * (STAGE_U * 4) + soff;
        cp16(ab,      Ag + kc);
        cp16(ab + 16, Ag + kc + 8);
        cp16(bb,      Bg + kc);
        cp16(bb + 16, Bg + kc + 8);
        CP_COMMIT();
    }

    for (int it = 0; it < KCHUNKS; it++) {
        CP_WAIT1();
        __syncthreads();
        uint32_t aS = sAs + (it % NSTG) * (STAGE_U * 4) + a_off;
        uint32_t bS = sBs + (it % NSTG) * (STAGE_U * 4) + b_off;
#pragma unroll
        for (int ks = 0; ks < 2; ks++) {
            uint32_t af[4][4], bf[4][2];
#pragma unroll
            for (int mt = 0; mt < 4; mt++)
                ldsm_x4(af[mt], aS + mt * (16 * 80) + ks * 32);
#pragma unroll
            for (int j = 0; j < 2; j++)
                ldsm_x4(&bf[2 * j][0], bS + j * (16 * 80) + ks * 32);   // fills bf[2j],bf[2j+1]
#pragma unroll
            for (int mt = 0; mt < 4; mt++)
#pragma unroll
                for (int nt = 0; nt < 4; nt++)
                    mma_bf16(acc[mt][nt], af[mt], bf[nt]);
        }
        __syncthreads();
        if (it + 2 < KCHUNKS) {
            int s = (it + 2) % NSTG;
            int kc = (it + 2) * 32;
            uint32_t ab = sAs + s * (STAGE_U * 4) + soff;
            uint32_t bb = sBs + s * (STAGE_U * 4) + soff;
            cp16(ab,      Ag + kc);
            cp16(ab + 16, Ag + kc + 8);
            cp16(bb,      Bg + kc);
            cp16(bb + 16, Bg + kc + 8);
        }
        CP_COMMIT();
    }

#pragma unroll
    for (int mt = 0; mt < 4; mt++) {
        size_t r0 = (size_t)(bm + wr * 64 + mt * 16 + lg);
#pragma unroll
        for (int nt = 0; nt < 4; nt++) {
            int c0 = bn + wc * 32 + nt * 8 + lk * 2;
            float bx = bias[c0], by = bias[c0 + 1];
            float2 v0 = make_float2(acc[mt][nt][0] + bx, acc[mt][nt][1] + by);
            float2 v1 = make_float2(acc[mt][nt][2] + bx, acc[mt][nt][3] + by);
            *(float2*)(C + r0 * N + c0) = v0;
            *(float2*)(C + (r0 + 8) * N + c0) = v1;
        }
    }
}

// ---------------- temporal attention, S=16 ----------------
__global__ __launch_bounds__(256) void attn16_kernel(
    const float* __restrict__ qkv, __nv_bfloat16* __restrict__ out)
{
    __shared__ __align__(16) float Qs[16][68];
    __shared__ __align__(16) float Ks[16][68];
    __shared__ __align__(16) float Vs[16][64];
    __shared__ float Ps[16][17];

    int h = blockIdx.y;
    int seq = blockIdx.x;
    int b = seq / Pp, p = seq % Pp;
    int base = b * Ff * Pp + p;
    int tid = threadIdx.x;

#pragma unroll
    for (int i = 0; i < 4; i++) {
        int idx = i * 256 + tid;
        int f = idx >> 6, d = idx & 63;
        size_t row = (size_t)(base + f * Pp) * QKVW + h * HD + d;
        Qs[f][d] = qkv[row];
        Ks[f][d] = qkv[row + Dd];
        Vs[f][d] = qkv[row + 2 * Dd];
    }
    __syncthreads();

    {
        int q = tid >> 4, k = tid & 15;
        float acc = 0.f;
#pragma unroll
        for (int d4 = 0; d4 < 16; d4++) {
            float4 kv = *(const float4*)(&Ks[k][d4 * 4]);
            float4 qv = *(const float4*)(&Qs[q][d4 * 4]);
            acc += qv.x * kv.x + qv.y * kv.y + qv.z * kv.z + qv.w * kv.w;
        }
        acc *= 0.125f;
        float m = acc;
#pragma unroll
        for (int o = 8; o; o >>= 1) m = fmaxf(m, __shfl_xor_sync(0xffffffffu, m, o));
        float e = __expf(acc - m);
        float s = e;
#pragma unroll
        for (int o = 8; o; o >>= 1) s += __shfl_xor_sync(0xffffffffu, s, o);
        Ps[q][k] = e / s;
    }
    __syncthreads();

    {
        int d = tid & 63;
        int q0 = (tid >> 6) * 4;
        float a0 = 0.f, a1 = 0.f, a2 = 0.f, a3 = 0.f;
#pragma unroll
        for (int k = 0; k < 16; k++) {
            float v = Vs[k][d];
            a0 += Ps[q0 + 0][k] * v;
            a1 += Ps[q0 + 1][k] * v;
            a2 += Ps[q0 + 2][k] * v;
            a3 += Ps[q0 + 3][k] * v;
        }
        size_t o0 = (size_t)(base + (q0 + 0) * Pp) * Dd + h * HD + d;
        out[o0]                       = __float2bfloat16(a0);
        out[o0 + (size_t)Pp * Dd]     = __float2bfloat16(a1);
        out[o0 + (size_t)2 * Pp * Dd] = __float2bfloat16(a2);
        out[o0 + (size_t)3 * Pp * Dd] = __float2bfloat16(a3);
    }
}

// ---------------- spatial attention, S=196 padded to 208, bf16 MMA ----------
#define SPAD 208
#define QRU 36
#define VTR 108
__global__ __launch_bounds__(256) void attn196_kernel(
    const float* __restrict__ qkv, __nv_bfloat16* __restrict__ out)
{
    extern __shared__ __align__(16) uint32_t sm196[];
    uint32_t* Qu = sm196;
    uint32_t* Ku = Qu + SPAD * QRU;
    uint32_t* Vu = Ku + SPAD * QRU;
    uint32_t* Tu = Vu + SPAD * QRU;

    int h = blockIdx.y;
    int base = blockIdx.x * Pp;
    int tid = threadIdx.x;
    int wid = tid >> 5, lane = tid & 31;
    int lg = lane >> 2, lk = lane & 3;

    for (int i = tid; i < SPAD * 32; i += 256) {
        int s = i >> 5, d2 = i & 31;
        uint32_t qv = 0, kv = 0, vv = 0;
        if (s < Pp) {
            const float* row = qkv + (size_t)(base + s) * QKVW + h * HD + d2 * 2;
            float2 q2 = *(const float2*)(row);
            float2 k2 = *(const float2*)(row + Dd);
            float2 v2 = *(const float2*)(row + 2 * Dd);
            qv = packbf(q2.x, q2.y);
            kv = packbf(k2.x, k2.y);
            vv = packbf(v2.x, v2.y);
        }
        Qu[s * QRU + d2] = qv;
        Ku[s * QRU + d2] = kv;
        Vu[s * QRU + d2] = vv;
    }
    __syncthreads();

    {
        const __nv_bfloat16* vb = (const __nv_bfloat16*)Vu;
        for (int i = tid; i < 64 * 104; i += 256) {
            int d = i & 63, s2 = i >> 6;
            uint32_t lo = *(const uint16_t*)(vb + (2 * s2) * (QRU * 2) + d);
            uint32_t hi = *(const uint16_t*)(vb + (2 * s2 + 1) * (QRU * 2) + d);
            Tu[d * VTR + s2] = lo | (hi << 16);
        }
    }
    __syncthreads();

    for (int mt = wid; mt < 13; mt += 8) {
        int r = mt * 16 + lg;

        uint32_t qa[4][4];
#pragma unroll
        for (int kc = 0; kc < 4; kc++) {
            int c2 = kc * 8 + lk;
            qa[kc][0] = Qu[r * QRU + c2];
            qa[kc][1] = Qu[(r + 8) * QRU + c2];
            qa[kc][2] = Qu[r * QRU + c2 + 4];
            qa[kc][3] = Qu[(r + 8) * QRU + c2 + 4];
        }

        float sc[26][4];
#pragma unroll
        for (int nt = 0; nt < 26; nt++)
            sc[nt][0] = sc[nt][1] = sc[nt][2] = sc[nt][3] = 0.f;
#pragma unroll
        for (int nt = 0; nt < 26; nt++) {
            int n = nt * 8 + lg;
#pragma unroll
            for (int kc = 0; kc < 4; kc++) {
                uint32_t b[2];
                b[0] = Ku[n * QRU + kc * 8 + lk];
                b[1] = Ku[n * QRU + kc * 8 + lk + 4];
                mma_bf16(sc[nt], qa[kc], b);
            }
        }

#pragma unroll
        for (int nt = 0; nt < 26; nt++) {
            int col0 = nt * 8 + 2 * lk;
            sc[nt][0] = (col0     < Pp) ? sc[nt][0] * 0.125f : -1e30f;
            sc[nt][1] = (col0 + 1 < Pp) ? sc[nt][1] * 0.125f : -1e30f;
            sc[nt][2] = (col0     < Pp) ? sc[nt][2] * 0.125f : -1e30f;
            sc[nt][3] = (col0 + 1 < Pp) ? sc[nt][3] * 0.125f : -1e30f;
        }

        float m0 = -1e30f, m1 = -1e30f;
#pragma unroll
        for (int nt = 0; nt < 26; nt++) {
            m0 = fmaxf(m0, fmaxf(sc[nt][0], sc[nt][1]));
            m1 = fmaxf(m1, fmaxf(sc[nt][2], sc[nt][3]));
        }
        m0 = fmaxf(m0, __shfl_xor_sync(0xffffffffu, m0, 1));
        m0 = fmaxf(m0, __shfl_xor_sync(0xffffffffu, m0, 2));
        m1 = fmaxf(m1, __shfl_xor_sync(0xffffffffu, m1, 1));
        m1 = fmaxf(m1, __shfl_xor_sync(0xffffffffu, m1, 2));

        float s0 = 0.f, s1 = 0.f;
#pragma unroll
        for (int nt = 0; nt < 26; nt++) {
            sc[nt][0] = __expf(sc[nt][0] - m0); s0 += sc[nt][0];
            sc[nt][1] = __expf(sc[nt][1] - m0); s0 += sc[nt][1];
            sc[nt][2] = __expf(sc[nt][2] - m1); s1 += sc[nt][2];
            sc[nt][3] = __expf(sc[nt][3] - m1); s1 += sc[nt][3];
        }
        s0 += __shfl_xor_sync(0xffffffffu, s0, 1);
        s0 += __shfl_xor_sync(0xffffffffu, s0, 2);
        s1 += __shfl_xor_sync(0xffffffffu, s1, 1);
        s1 += __shfl_xor_sync(0xffffffffu, s1, 2);

        uint32_t pk[13][4];
#pragma unroll
        for (int j = 0; j < 13; j++) {
            pk[j][0] = packbf(sc[2 * j][0],     sc[2 * j][1]);
            pk[j][1] = packbf(sc[2 * j][2],     sc[2 * j][3]);
            pk[j][2] = packbf(sc[2 * j + 1][0], sc[2 * j + 1][1]);
            pk[j][3] = packbf(sc[2 * j + 1][2], sc[2 * j + 1][3]);
        }

        float oa[8][4];
#pragma unroll
        for (int nd = 0; nd < 8; nd++)
            oa[nd][0] = oa[nd][1] = oa[nd][2] = oa[nd][3] = 0.f;
#pragma unroll
        for (int j = 0; j < 13; j++) {
#pragma unroll
            for (int nd = 0; nd < 8; nd++) {
                int n = nd * 8 + lg;
                uint32_t b[2];
                b[0] = Tu[n * VTR + j * 8 + lk];
                b[1] = Tu[n * VTR + j * 8 + lk + 4];
                mma_bf16(oa[nd], pk[j], b);
            }
        }

        float inv0 = 1.0f / s0, inv1 = 1.0f / s1;
        int row0 = r, row1 = r + 8;
#pragma unroll
        for (int nd = 0; nd < 8; nd++) {
            int col = nd * 8 + 2 * lk;
            if (row0 < Pp) {
                uint32_t u = packbf(oa[nd][0] * inv0, oa[nd][1] * inv0);
                *(uint32_t*)(out + (size_t)(base + row0) * Dd + h * HD + col) = u;
            }
            if (row1 < Pp) {
                uint32_t u = packbf(oa[nd][2] * inv1, oa[nd][3] * inv1);
                *(uint32_t*)(out + (size_t)(base + row1) * Dd + h * HD + col) = u;
            }
        }
    }
}

// ---------------- fused residual + LayerNorm (+ optional bf16 copy) ----------
__global__ __launch_bounds__(256) void add_ln_kernel(
    const float* __restrict__ x, const float* __restrict__ y,
    const float* __restrict__ g, const float* __restrict__ b,
    float* __restrict__ out, __nv_bfloat16* __restrict__ outb, int wb)
{
    __shared__ float row_sm[Dd];
    __shared__ float ps[8], ps2[8];
    __shared__ float red[2];

    size_t row = blockIdx.x;
    const float* xr = x + row * Dd;
    const float* yr = y + row * Dd;
    int tid = threadIdx.x;
    int lane = tid & 31, wid = tid >> 5;

    float s = 0.f, s2 = 0.f;
    for (int d = tid; d < Dd; d += 256) {
        float v = xr[d] + yr[d];
        row_sm[d] = v;
        s += v;
        s2 += v * v;
    }
#pragma unroll
    for (int o = 16; o; o >>= 1) {
        s  += __shfl_xor_sync(0xffffffffu, s, o);
        s2 += __shfl_xor_sync(0xffffffffu, s2, o);
    }
    if (lane == 0) { ps[wid] = s; ps2[wid] = s2; }
    __syncthreads();
    if (tid < 8) {
        s = ps[tid]; s2 = ps2[tid];
#pragma unroll
        for (int o = 4; o; o >>= 1) {
            s  += __shfl_xor_sync(0xffu, s, o);
            s2 += __shfl_xor_sync(0xffu, s2, o);
        }
        if (tid == 0) {
            float mean = s / Dd;
            float var = s2 / Dd - mean * mean;
            red[0] = mean;
            red[1] = rsqrtf(var + 1e-5f);
        }
    }
    __syncthreads();
    float mean = red[0], rstd = red[1];
    for (int d = tid; d < Dd; d += 256) {
        float v = (row_sm[d] - mean) * rstd * g[d] + b[d];
        out[row * Dd + d] = v;
        if (wb) outb[row * Dd + d] = __float2bfloat16(v);
    }
}

// ---------------- launch ----------------
extern "C" void kernel_launch(void* const* d_in, const int* in_sizes, int n_in,
                              void* d_out, int out_size)
{
    const float* x      = (const float*)d_in[0];
    const float* Wqkv_t = (const float*)d_in[1];
    const float* bqkv_t = (const float*)d_in[2];
    const float* Wo_t   = (const float*)d_in[3];
    const float* bo_t   = (const float*)d_in[4];
    const float* Wqkv_s = (const float*)d_in[5];
    const float* bqkv_s = (const float*)d_in[6];
    const float* Wo_s   = (const float*)d_in[7];
    const float* bo_s   = (const float*)d_in[8];
    const float* g1     = (const float*)d_in[9];
    const float* b1     = (const float*)d_in[10];
    const float* g2     = (const float*)d_in[11];
    const float* b2     = (const float*)d_in[12];
    float* out = (float*)d_out;

    float *qkv, *y, *x1;
    __nv_bfloat16 *xb, *x1b, *attnb, *wtb;
    cudaGetSymbolAddress((void**)&qkv,   g_qkv);
    cudaGetSymbolAddress((void**)&y,     g_y);
    cudaGetSymbolAddress((void**)&x1,    g_x1);
    cudaGetSymbolAddress((void**)&xb,    g_xb);
    cudaGetSymbolAddress((void**)&x1b,   g_x1b);
    cudaGetSymbolAddress((void**)&attnb, g_attnb);
    cudaGetSymbolAddress((void**)&wtb,   g_wtb);

    const int SMEM196 = (3 * SPAD * QRU + 64 * VTR) * (int)sizeof(uint32_t);  // 117504
    cudaFuncSetAttribute(attn196_kernel, cudaFuncAttributeMaxDynamicSharedMemorySize, SMEM196);

    dim3 tb(32, 8);
    dim3 tg_qkv(QKVW / 32, GK / 32);      // (72, 24)
    dim3 tg_out(Dd / 32, GK / 32);        // (24, 24)
    dim3 gg_qkv(QKVW / 128, NTOK / 128);  // (18, 196)
    dim3 gg_out(Dd / 128, NTOK / 128);    // (6, 196)
    int n4 = NTOK * Dd / 4;

    // x -> bf16
    f2b_kernel<<<(n4 + 255) / 256, 256>>>(x, xb, n4);
    // temporal QKV projection
    transpose_b<<<tg_qkv, tb>>>(Wqkv_t, wtb, GK, QKVW);
    gemm_mma<<<gg_qkv, 256>>>(xb, wtb, bqkv_t, qkv, QKVW);
    // temporal attention (S=16)
    attn16_kernel<<<dim3(Bb * Pp, Hh), 256>>>(qkv, attnb);
    // temporal out-projection
    transpose_b<<<tg_out, tb>>>(Wo_t, wtb, GK, Dd);
    gemm_mma<<<gg_out, 256>>>(attnb, wtb, bo_t, y, Dd);
    // x1 = LN(x + y)  (+ bf16 copy)
    add_ln_kernel<<<NTOK, 256>>>(x, y, g1, b1, x1, x1b, 1);
    // spatial QKV projection
    transpose_b<<<tg_qkv, tb>>>(Wqkv_s, wtb, GK, QKVW);
    gemm_mma<<<gg_qkv, 256>>>(x1b, wtb, bqkv_s, qkv, QKVW);
    // spatial attention (S=196), bf16 MMA flash-style
    attn196_kernel<<<dim3(Bb * Ff, Hh), 256, SMEM196>>>(qkv, attnb);
    // spatial out-projection
    transpose_b<<<tg_out, tb>>>(Wo_s, wtb, GK, Dd);
    gemm_mma<<<gg_out, 256>>>(attnb, wtb, bo_s, y, Dd);
    // out = LN(x1 + y)
    add_ln_kernel<<<NTOK, 256>>>(x1, y, g2, b2, out, (__nv_bfloat16*)nullptr, 0);
}